// round 1
// baseline (speedup 1.0000x reference)
#include <cuda_runtime.h>
#include <cuda_bf16.h>
#include <math.h>

// Problem dims
#define BB 4
#define SS 2048
#define II 512
#define DD 512
#define HH 8
#define HD 64
#define PP 720
#define NT (BB*SS)        // 8192 tokens

// ---------------- scratch (__device__ globals, no allocation) ----------------
__device__ float g_q[(size_t)NT * DD];                 // [B,S,H*HD]
__device__ float g_k[(size_t)NT * DD];
__device__ float g_v[(size_t)NT * DD];
__device__ float g_sc[(size_t)BB * HH * SS * SS];      // 512 MB scores/attn
__device__ float g_comb[(size_t)NT * DD];              // [B,S,D]
__device__ float g_up[(size_t)BB * PP * DD];           // [B,P,D]

// ---------------- generic strided batched SGEMM ----------------
// C[m,n] = alpha * sum_k A[m,k]*B[k,n]  (+bias), batched over blockIdx.z with
// split outer/inner batch strides: off = (z/z_inner)*bo + (z%z_inner)*bi.
// A[m,k] at Ab[m*a_rs + k*a_cs]; B[k,n] at Bb[k*b_rs + n*b_cs];
// C[m,n] at Cb[m*c_rs + n] (col stride 1 always).
// bias_mode: 0 none, 1 per-n, 2 per-m.
#define TBM 64
#define TBN 64
#define TBK 16

__global__ __launch_bounds__(256)
void sgemm_generic(
    int M, int N, int K, float alpha,
    const float* __restrict__ A, long a_bo, long a_bi, int a_rs, int a_cs,
    const float* __restrict__ B, long b_bo, long b_bi, int b_rs, int b_cs,
    float* __restrict__ C, long c_bo, long c_bi, int c_rs,
    const float* __restrict__ bias, int bias_mode, long bias_bo, long bias_bi,
    int z_inner)
{
    const int z  = blockIdx.z;
    const int zo = z / z_inner;
    const int zi = z % z_inner;
    const float* Ab = A + (long)zo * a_bo + (long)zi * a_bi;
    const float* Bb = B + (long)zo * b_bo + (long)zi * b_bi;
    float*       Cb = C + (long)zo * c_bo + (long)zi * c_bi;
    const float* biasb = bias ? bias + (long)zo * bias_bo + (long)zi * bias_bi : nullptr;

    const int m0 = blockIdx.y * TBM;
    const int n0 = blockIdx.x * TBN;

    __shared__ float As[TBK][TBM + 1];
    __shared__ float Bs[TBK][TBN + 1];

    const int tid = threadIdx.x;
    const int tx = tid & 15;        // 0..15 -> n
    const int ty = tid >> 4;        // 0..15 -> m

    float acc[4][4] = {};

    for (int k0 = 0; k0 < K; k0 += TBK) {
        // --- load A tile: k-fastest (A is row-major with a_cs==1 in all uses)
        #pragma unroll
        for (int i = 0; i < 4; i++) {
            int e = tid + i * 256;
            int k = e & (TBK - 1);
            int m = e >> 4;
            float v = 0.f;
            if (m0 + m < M)
                v = Ab[(long)(m0 + m) * a_rs + (long)(k0 + k) * a_cs];
            As[k][m] = v;
        }
        // --- load B tile: pick the mapping that coalesces global reads
        if (b_cs == 1) {
            #pragma unroll
            for (int i = 0; i < 4; i++) {
                int e = tid + i * 256;
                int n = e & (TBN - 1);
                int k = e >> 6;
                float v = 0.f;
                if (n0 + n < N)
                    v = Bb[(long)(k0 + k) * b_rs + (long)(n0 + n)];
                Bs[k][n] = v;
            }
        } else {
            #pragma unroll
            for (int i = 0; i < 4; i++) {
                int e = tid + i * 256;
                int k = e & (TBK - 1);
                int n = e >> 4;
                float v = 0.f;
                if (n0 + n < N)
                    v = Bb[(long)(k0 + k) * b_rs + (long)(n0 + n) * b_cs];
                Bs[k][n] = v;
            }
        }
        __syncthreads();

        #pragma unroll
        for (int kk = 0; kk < TBK; kk++) {
            float ar[4], br[4];
            #pragma unroll
            for (int i = 0; i < 4; i++) ar[i] = As[kk][ty * 4 + i];
            #pragma unroll
            for (int j = 0; j < 4; j++) br[j] = Bs[kk][tx * 4 + j];
            #pragma unroll
            for (int i = 0; i < 4; i++)
                #pragma unroll
                for (int j = 0; j < 4; j++)
                    acc[i][j] = fmaf(ar[i], br[j], acc[i][j]);
        }
        __syncthreads();
    }

    #pragma unroll
    for (int i = 0; i < 4; i++) {
        int m = m0 + ty * 4 + i;
        if (m >= M) continue;
        #pragma unroll
        for (int j = 0; j < 4; j++) {
            int n = n0 + tx * 4 + j;
            if (n >= N) continue;
            float v = acc[i][j] * alpha;
            if (bias_mode == 1)      v += biasb[n];
            else if (bias_mode == 2) v += biasb[m];
            Cb[(long)m * c_rs + n] = v;
        }
    }
}

// ---------------- row softmax over length-2048 rows ----------------
__global__ __launch_bounds__(256)
void softmax_rows2048(float* __restrict__ S)
{
    const long row = blockIdx.x;
    float* p = S + row * (long)SS;
    const int tid = threadIdx.x;

    float vals[8];
    float mx = -INFINITY;
    #pragma unroll
    for (int i = 0; i < 8; i++) {
        vals[i] = p[tid + i * 256];
        mx = fmaxf(mx, vals[i]);
    }
    __shared__ float red[256];
    red[tid] = mx;
    __syncthreads();
    #pragma unroll
    for (int s = 128; s > 0; s >>= 1) {
        if (tid < s) red[tid] = fmaxf(red[tid], red[tid + s]);
        __syncthreads();
    }
    mx = red[0];
    __syncthreads();

    float sum = 0.f;
    #pragma unroll
    for (int i = 0; i < 8; i++) {
        vals[i] = __expf(vals[i] - mx);
        sum += vals[i];
    }
    red[tid] = sum;
    __syncthreads();
    #pragma unroll
    for (int s = 128; s > 0; s >>= 1) {
        if (tid < s) red[tid] += red[tid + s];
        __syncthreads();
    }
    const float inv = 1.f / red[0];
    #pragma unroll
    for (int i = 0; i < 8; i++)
        p[tid + i * 256] = vals[i] * inv;
}

// ---------------- launch ----------------
extern "C" void kernel_launch(void* const* d_in, const int* in_sizes, int n_in,
                              void* d_out, int out_size)
{
    (void)in_sizes; (void)n_in; (void)out_size;
    const float* x  = (const float*)d_in[0];
    const float* Wq = (const float*)d_in[1];
    const float* bq = (const float*)d_in[2];
    const float* Wk = (const float*)d_in[3];
    const float* bk = (const float*)d_in[4];
    const float* Wv = (const float*)d_in[5];
    const float* bv = (const float*)d_in[6];
    const float* Wt = (const float*)d_in[7];
    const float* bt = (const float*)d_in[8];
    const float* Wo = (const float*)d_in[9];
    const float* bo = (const float*)d_in[10];
    float* out = (float*)d_out;

    float *q, *k, *v, *sc, *comb, *up;
    cudaGetSymbolAddress((void**)&q,    g_q);
    cudaGetSymbolAddress((void**)&k,    g_k);
    cudaGetSymbolAddress((void**)&v,    g_v);
    cudaGetSymbolAddress((void**)&sc,   g_sc);
    cudaGetSymbolAddress((void**)&comb, g_comb);
    cudaGetSymbolAddress((void**)&up,   g_up);

    dim3 blk(256);

    // 1) QKV per-head projections: [8192,512] @ [512,64] per head -> [B,S,H*HD]
    {
        dim3 grid(1, NT / TBM, HH);
        sgemm_generic<<<grid, blk>>>(NT, HD, II, 1.f,
            x,  0, 0, II, 1,
            Wq, 0, (long)II * HD, HD, 1,
            q,  0, HD, DD,
            bq, 1, 0, HD, HH);
        sgemm_generic<<<grid, blk>>>(NT, HD, II, 1.f,
            x,  0, 0, II, 1,
            Wk, 0, (long)II * HD, HD, 1,
            k,  0, HD, DD,
            bk, 1, 0, HD, HH);
        sgemm_generic<<<grid, blk>>>(NT, HD, II, 1.f,
            x,  0, 0, II, 1,
            Wv, 0, (long)II * HD, HD, 1,
            v,  0, HD, DD,
            bv, 1, 0, HD, HH);
    }

    // 2) scores = Q K^T / HD   per (b,h); z = b*H + h
    {
        const long qb_o = (long)SS * DD;       // per-b stride in q/k
        const long sc_o = (long)HH * SS * SS;  // per-b stride in scores
        const long sc_i = (long)SS * SS;       // per-h
        dim3 grid(SS / TBN, SS / TBM, BB * HH);
        sgemm_generic<<<grid, blk>>>(SS, SS, HD, 1.f / (float)HD,
            q,  qb_o, HD, DD, 1,
            k,  qb_o, HD, 1, DD,          // K^T: k-index contiguous
            sc, sc_o, sc_i, SS,
            nullptr, 0, 0, 0, HH);
    }

    // 3) softmax over last dim
    softmax_rows2048<<<dim3(BB * HH * SS), blk>>>(sc);

    // 4) ctx = attn @ V  -> written straight into concat layout [B,S,D]
    {
        const long sc_o = (long)HH * SS * SS;
        const long sc_i = (long)SS * SS;
        const long vb_o = (long)SS * DD;
        dim3 grid(1, SS / TBM, BB * HH);
        sgemm_generic<<<grid, blk>>>(SS, HD, SS, 1.f,
            sc, sc_o, sc_i, SS, 1,
            v,  vb_o, HD, DD, 1,
            comb, vb_o, HD, DD,
            nullptr, 0, 0, 0, HH);
    }

    // 5) up[b,p,d] = sum_s Wt[p,s] * comb[b,s,d] + bt[p]
    {
        dim3 grid(DD / TBN, (PP + TBM - 1) / TBM, BB);
        sgemm_generic<<<grid, blk>>>(PP, DD, SS, 1.f,
            Wt, 0, 0, SS, 1,
            comb, 0, (long)SS * DD, DD, 1,
            up, 0, (long)PP * DD, DD,
            bt, 2, 0, 0, BB);
    }

    // 6) out[b,p,o] = sum_d up[b,p,d] * Wo[o,d] + bo[o]
    {
        dim3 grid(II / TBN, (PP + TBM - 1) / TBM, BB);
        sgemm_generic<<<grid, blk>>>(PP, II, DD, 1.f,
            up, 0, (long)PP * DD, DD, 1,
            Wo, 0, 0, 1, DD,              // Wo^T: k(d)-index contiguous
            out, 0, (long)PP * II, II,
            bo, 1, 0, 0, BB);
    }
}

// round 2
// speedup vs baseline: 1.4504x; 1.4504x over previous
#include <cuda_runtime.h>
#include <cuda_bf16.h>
#include <math.h>
#include <stdint.h>

// Problem dims
#define BB 4
#define SS 2048
#define II 512
#define DD 512
#define HH 8
#define HD 64
#define PP 720
#define NT (BB*SS)        // 8192 tokens
#define QKVW (3*DD)       // 1536

// ---------------- scratch (__device__ globals, no allocation) ----------------
__device__ float g_qkv[(size_t)NT * QKVW];             // [B,S, q|k|v]
__device__ float g_sc[(size_t)BB * HH * SS * SS];      // 512 MB scores/attn
__device__ float g_comb[(size_t)NT * DD];              // [B,S,D]
__device__ float g_up[(size_t)BB * PP * DD];           // [B,P,D]
__device__ float g_wp[(size_t)II * QKVW];              // packed QKV weights [I, 3*D]
__device__ float g_bp[QKVW];                           // packed QKV bias

// ---------------- weight packing ----------------
// Wp[i*1536 + m*512 + h*64 + d] = W_m[h*512*64 + i*64 + d]
__global__ void pack_qkv_w(const float* __restrict__ Wq,
                           const float* __restrict__ Wk,
                           const float* __restrict__ Wv,
                           float* __restrict__ Wp)
{
    int idx = blockIdx.x * blockDim.x + threadIdx.x;    // 0 .. 3*512*512-1
    if (idx >= 3 * II * DD) return;
    int m   = idx / (II * DD);
    int rem = idx % (II * DD);          // = h*(512*64) + i*64 + d
    int h   = rem / (II * HD);
    int i   = (rem / HD) % II;
    int d   = rem % HD;
    const float* src = (m == 0) ? Wq : (m == 1) ? Wk : Wv;
    Wp[(long)i * QKVW + m * DD + h * HD + d] = src[rem];
}

__global__ void pack_qkv_b(const float* __restrict__ bq,
                           const float* __restrict__ bk,
                           const float* __restrict__ bv,
                           float* __restrict__ bp)
{
    int idx = blockIdx.x * blockDim.x + threadIdx.x;
    if (idx >= QKVW) return;
    int m = idx / DD;
    int r = idx % DD;                   // = h*64+d, matches source layout
    const float* src = (m == 0) ? bq : (m == 1) ? bk : bv;
    bp[idx] = src[r];
}

// ---------------- bf16x3 tensor-core GEMM ----------------
// C = alpha * A @ B (+bias). A row-major, k contiguous (a_cs==1 always).
// B[k,n] at Bb[k*b_rs + n*b_cs]. Batched over blockIdx.z with split strides.
#define BM 128
#define BN 64
#define BK 32
#define KP 40   // padded smem row stride (bf16 elems)

__device__ __forceinline__ uint32_t lds_u32(const __nv_bfloat16* p) {
    return *(const uint32_t*)p;
}

__device__ __forceinline__ void mma_bf16(float* c, const uint32_t* a, const uint32_t* b) {
    asm volatile(
        "mma.sync.aligned.m16n8k16.row.col.f32.bf16.bf16.f32 "
        "{%0,%1,%2,%3}, {%4,%5,%6,%7}, {%8,%9}, {%0,%1,%2,%3};\n"
        : "+f"(c[0]), "+f"(c[1]), "+f"(c[2]), "+f"(c[3])
        : "r"(a[0]), "r"(a[1]), "r"(a[2]), "r"(a[3]), "r"(b[0]), "r"(b[1]));
}

__device__ __forceinline__ void split_bf16(float x, __nv_bfloat16& h, __nv_bfloat16& l) {
    h = __float2bfloat16(x);
    l = __float2bfloat16(x - __bfloat162float(h));
}

__global__ __launch_bounds__(256)
void gemm_bf16x3(
    int M, int N, int K, float alpha,
    const float* __restrict__ A, long a_bo, long a_bi, int a_rs,
    const float* __restrict__ B, long b_bo, long b_bi, int b_rs, int b_cs,
    float* __restrict__ C, long c_bo, long c_bi, int c_rs,
    const float* __restrict__ bias, int bias_mode, long bias_bo, long bias_bi,
    int z_inner)
{
    const int z  = blockIdx.z;
    const int zo = z / z_inner;
    const int zi = z % z_inner;
    const float* Ab = A + (long)zo * a_bo + (long)zi * a_bi;
    const float* Bb = B + (long)zo * b_bo + (long)zi * b_bi;
    float*       Cb = C + (long)zo * c_bo + (long)zi * c_bi;
    const float* biasb = bias ? bias + (long)zo * bias_bo + (long)zi * bias_bi : nullptr;

    const int m0 = blockIdx.y * BM;
    const int n0 = blockIdx.x * BN;

    __shared__ __nv_bfloat16 Ah[BM][KP], Al[BM][KP];
    __shared__ __nv_bfloat16 Bh[BN][KP], Bl[BN][KP];

    const int tid  = threadIdx.x;
    const int lane = tid & 31;
    const int warp = tid >> 5;
    const int wm = (warp & 3) * 32;     // warp m origin within block
    const int wn = (warp >> 2) * 32;    // warp n origin within block
    const int qr = lane >> 2;           // 0..7
    const int qc = (lane & 3) * 2;      // 0,2,4,6

    float acc[2][4][4] = {};            // [mtile][ntile][frag]

    for (int k0 = 0; k0 < K; k0 += BK) {
        // --- load A tile (float4, k-contiguous), split to hi/lo bf16
        #pragma unroll
        for (int i = 0; i < 4; i++) {
            int e  = tid + i * 256;
            int m  = e >> 3;
            int kq = (e & 7) * 4;
            float4 val = make_float4(0.f, 0.f, 0.f, 0.f);
            if (m0 + m < M)
                val = *(const float4*)(Ab + (long)(m0 + m) * a_rs + k0 + kq);
            float xs[4] = {val.x, val.y, val.z, val.w};
            #pragma unroll
            for (int j = 0; j < 4; j++) {
                __nv_bfloat16 h, l; split_bf16(xs[j], h, l);
                Ah[m][kq + j] = h; Al[m][kq + j] = l;
            }
        }
        // --- load B tile, store transposed [n][k]
        if (b_cs == 1) {
            #pragma unroll
            for (int i = 0; i < 8; i++) {
                int e  = tid + i * 256;
                int n  = e & 63;
                int kk = e >> 6;
                float v = Bb[(long)(k0 + kk) * b_rs + (n0 + n)];
                __nv_bfloat16 h, l; split_bf16(v, h, l);
                Bh[n][kk] = h; Bl[n][kk] = l;
            }
        } else {
            #pragma unroll
            for (int i = 0; i < 8; i++) {
                int e  = tid + i * 256;
                int kk = e & 31;
                int n  = e >> 5;
                float v = Bb[(long)(k0 + kk) * b_rs + (long)(n0 + n) * b_cs];
                __nv_bfloat16 h, l; split_bf16(v, h, l);
                Bh[n][kk] = h; Bl[n][kk] = l;
            }
        }
        __syncthreads();

        #pragma unroll
        for (int ks = 0; ks < 2; ks++) {
            const int kc = ks * 16 + qc;
            uint32_t ah[2][4], al[2][4], bh[4][2], bl[4][2];
            #pragma unroll
            for (int mt = 0; mt < 2; mt++) {
                int r0 = wm + mt * 16 + qr;
                ah[mt][0] = lds_u32(&Ah[r0    ][kc    ]);
                ah[mt][1] = lds_u32(&Ah[r0 + 8][kc    ]);
                ah[mt][2] = lds_u32(&Ah[r0    ][kc + 8]);
                ah[mt][3] = lds_u32(&Ah[r0 + 8][kc + 8]);
                al[mt][0] = lds_u32(&Al[r0    ][kc    ]);
                al[mt][1] = lds_u32(&Al[r0 + 8][kc    ]);
                al[mt][2] = lds_u32(&Al[r0    ][kc + 8]);
                al[mt][3] = lds_u32(&Al[r0 + 8][kc + 8]);
            }
            #pragma unroll
            for (int nt = 0; nt < 4; nt++) {
                int nn = wn + nt * 8 + qr;
                bh[nt][0] = lds_u32(&Bh[nn][kc    ]);
                bh[nt][1] = lds_u32(&Bh[nn][kc + 8]);
                bl[nt][0] = lds_u32(&Bl[nn][kc    ]);
                bl[nt][1] = lds_u32(&Bl[nn][kc + 8]);
            }
            #pragma unroll
            for (int mt = 0; mt < 2; mt++)
                #pragma unroll
                for (int nt = 0; nt < 4; nt++) {
                    mma_bf16(acc[mt][nt], ah[mt], bh[nt]);
                    mma_bf16(acc[mt][nt], ah[mt], bl[nt]);
                    mma_bf16(acc[mt][nt], al[mt], bh[nt]);
                }
        }
        __syncthreads();
    }

    // --- epilogue
    #pragma unroll
    for (int mt = 0; mt < 2; mt++) {
        #pragma unroll
        for (int nt = 0; nt < 4; nt++) {
            int r0 = m0 + wm + mt * 16 + qr;
            int r1 = r0 + 8;
            int c  = n0 + wn + nt * 8 + qc;
            float bn0 = 0.f, bn1 = 0.f, bm0 = 0.f, bm1 = 0.f;
            if (bias_mode == 1) { bn0 = biasb[c]; bn1 = biasb[c + 1]; }
            if (r0 < M) {
                if (bias_mode == 2) bm0 = biasb[r0];
                Cb[(long)r0 * c_rs + c    ] = acc[mt][nt][0] * alpha + bn0 + bm0;
                Cb[(long)r0 * c_rs + c + 1] = acc[mt][nt][1] * alpha + bn1 + bm0;
            }
            if (r1 < M) {
                if (bias_mode == 2) bm1 = biasb[r1];
                Cb[(long)r1 * c_rs + c    ] = acc[mt][nt][2] * alpha + bn0 + bm1;
                Cb[(long)r1 * c_rs + c + 1] = acc[mt][nt][3] * alpha + bn1 + bm1;
            }
        }
    }
}

// ---------------- row softmax over length-2048 rows ----------------
__global__ __launch_bounds__(256)
void softmax_rows2048(float* __restrict__ S)
{
    const long row = blockIdx.x;
    float* p = S + row * (long)SS;
    const int tid = threadIdx.x;

    float vals[8];
    float mx = -INFINITY;
    #pragma unroll
    for (int i = 0; i < 8; i++) {
        vals[i] = p[tid + i * 256];
        mx = fmaxf(mx, vals[i]);
    }
    __shared__ float red[256];
    red[tid] = mx;
    __syncthreads();
    #pragma unroll
    for (int s = 128; s > 0; s >>= 1) {
        if (tid < s) red[tid] = fmaxf(red[tid], red[tid + s]);
        __syncthreads();
    }
    mx = red[0];
    __syncthreads();

    float sum = 0.f;
    #pragma unroll
    for (int i = 0; i < 8; i++) {
        vals[i] = __expf(vals[i] - mx);
        sum += vals[i];
    }
    red[tid] = sum;
    __syncthreads();
    #pragma unroll
    for (int s = 128; s > 0; s >>= 1) {
        if (tid < s) red[tid] += red[tid + s];
        __syncthreads();
    }
    const float inv = 1.f / red[0];
    #pragma unroll
    for (int i = 0; i < 8; i++)
        p[tid + i * 256] = vals[i] * inv;
}

// ---------------- launch ----------------
extern "C" void kernel_launch(void* const* d_in, const int* in_sizes, int n_in,
                              void* d_out, int out_size)
{
    (void)in_sizes; (void)n_in; (void)out_size;
    const float* x  = (const float*)d_in[0];
    const float* Wq = (const float*)d_in[1];
    const float* bq = (const float*)d_in[2];
    const float* Wk = (const float*)d_in[3];
    const float* bk = (const float*)d_in[4];
    const float* Wv = (const float*)d_in[5];
    const float* bv = (const float*)d_in[6];
    const float* Wt = (const float*)d_in[7];
    const float* bt = (const float*)d_in[8];
    const float* Wo = (const float*)d_in[9];
    const float* bo = (const float*)d_in[10];
    float* out = (float*)d_out;

    float *qkv, *sc, *comb, *up, *wp, *bp;
    cudaGetSymbolAddress((void**)&qkv,  g_qkv);
    cudaGetSymbolAddress((void**)&sc,   g_sc);
    cudaGetSymbolAddress((void**)&comb, g_comb);
    cudaGetSymbolAddress((void**)&up,   g_up);
    cudaGetSymbolAddress((void**)&wp,   g_wp);
    cudaGetSymbolAddress((void**)&bp,   g_bp);

    dim3 blk(256);

    // 0) pack QKV weights/bias into [I, 3*D] / [3*D]
    pack_qkv_w<<<(3 * II * DD + 255) / 256, 256>>>(Wq, Wk, Wv, wp);
    pack_qkv_b<<<(QKVW + 255) / 256, 256>>>(bq, bk, bv, bp);

    // 1) fused QKV: [8192,512] @ [512,1536] -> qkv
    {
        dim3 grid(QKVW / BN, NT / BM, 1);
        gemm_bf16x3<<<grid, blk>>>(NT, QKVW, II, 1.f,
            x,   0, 0, II,
            wp,  0, 0, QKVW, 1,
            qkv, 0, 0, QKVW,
            bp, 1, 0, 0, 1);
    }

    // 2) scores = Q K^T / HD   per (b,h); z = b*H + h
    {
        const long tok_b = (long)SS * QKVW;
        dim3 grid(SS / BN, SS / BM, BB * HH);
        gemm_bf16x3<<<grid, blk>>>(SS, SS, HD, 1.f / (float)HD,
            qkv,       tok_b, HD, QKVW,            // Q: a_bi = h*64
            qkv + DD,  tok_b, HD, 1, QKVW,          // K^T: b_rs=1 (d), b_cs=1536 (t)
            sc, (long)HH * SS * SS, (long)SS * SS, SS,
            nullptr, 0, 0, 0, HH);
    }

    // 3) softmax over last dim
    softmax_rows2048<<<dim3(BB * HH * SS), blk>>>(sc);

    // 4) ctx = attn @ V -> concat layout [B,S,D]
    {
        dim3 grid(HD / BN, SS / BM, BB * HH);
        gemm_bf16x3<<<grid, blk>>>(SS, HD, SS, 1.f,
            sc, (long)HH * SS * SS, (long)SS * SS, SS,
            qkv + 2 * DD, (long)SS * QKVW, HD, QKVW, 1,   // V: b_rs=1536 (t), b_cs=1 (d)
            comb, (long)SS * DD, HD, DD,
            nullptr, 0, 0, 0, HH);
    }

    // 5) up[b,p,d] = sum_s Wt[p,s] * comb[b,s,d] + bt[p]
    {
        dim3 grid(DD / BN, (PP + BM - 1) / BM, BB);
        gemm_bf16x3<<<grid, blk>>>(PP, DD, SS, 1.f,
            Wt,   0, 0, SS,
            comb, (long)SS * DD, 0, DD, 1,
            up,   (long)PP * DD, 0, DD,
            bt, 2, 0, 0, 1);
    }

    // 6) out[b,p,o] = sum_d up[b,p,d] * Wo[o,d] + bo[o]
    {
        dim3 grid(II / BN, (PP + BM - 1) / BM, BB);
        gemm_bf16x3<<<grid, blk>>>(PP, II, DD, 1.f,
            up, (long)PP * DD, 0, DD,
            Wo, 0, 0, 1, DD,                       // Wo^T: b_rs=1 (d), b_cs=512 (o)
            out, (long)PP * II, 0, II,
            bo, 1, 0, 0, 1);
    }
}

// round 3
// speedup vs baseline: 2.0737x; 1.4297x over previous
#include <cuda_runtime.h>
#include <cuda_bf16.h>
#include <math.h>
#include <stdint.h>

// Problem dims
#define BB 4
#define SS 2048
#define II 512
#define DD 512
#define HH 8
#define HD 64
#define PP 720
#define NT (BB*SS)        // 8192 tokens
#define QKVW (3*DD)       // 1536

// ---------------- scratch (__device__ globals, no allocation) ----------------
__device__ float g_qkv[(size_t)NT * QKVW];             // [B,S, q|k|v]
__device__ float g_comb[(size_t)NT * DD];              // [B,S,D]
__device__ float g_up[(size_t)BB * PP * DD];           // [B,P,D]
__device__ float g_wp[(size_t)II * QKVW];              // packed QKV weights [I, 3*D]
__device__ float g_bp[QKVW];                           // packed QKV bias

// ---------------- helpers ----------------
__device__ __forceinline__ uint32_t lds_u32(const __nv_bfloat16* p) {
    return *(const uint32_t*)p;
}
__device__ __forceinline__ void mma_bf16(float* c, const uint32_t* a, const uint32_t* b) {
    asm volatile(
        "mma.sync.aligned.m16n8k16.row.col.f32.bf16.bf16.f32 "
        "{%0,%1,%2,%3}, {%4,%5,%6,%7}, {%8,%9}, {%0,%1,%2,%3};\n"
        : "+f"(c[0]), "+f"(c[1]), "+f"(c[2]), "+f"(c[3])
        : "r"(a[0]), "r"(a[1]), "r"(a[2]), "r"(a[3]), "r"(b[0]), "r"(b[1]));
}
__device__ __forceinline__ void split_bf16(float x, __nv_bfloat16& h, __nv_bfloat16& l) {
    h = __float2bfloat16(x);
    l = __float2bfloat16(x - __bfloat162float(h));
}
__device__ __forceinline__ uint32_t packb(__nv_bfloat16 a, __nv_bfloat16 b) {
    __nv_bfloat162 t; t.x = a; t.y = b;
    return *(uint32_t*)&t;
}

// ---------------- weight packing ----------------
__global__ void pack_qkv_w(const float* __restrict__ Wq,
                           const float* __restrict__ Wk,
                           const float* __restrict__ Wv,
                           float* __restrict__ Wp)
{
    int idx = blockIdx.x * blockDim.x + threadIdx.x;
    if (idx >= 3 * II * DD) return;
    int m   = idx / (II * DD);
    int rem = idx % (II * DD);          // = h*(512*64) + i*64 + d
    int h   = rem / (II * HD);
    int i   = (rem / HD) % II;
    int d   = rem % HD;
    const float* src = (m == 0) ? Wq : (m == 1) ? Wk : Wv;
    Wp[(long)i * QKVW + m * DD + h * HD + d] = src[rem];
}

__global__ void pack_qkv_b(const float* __restrict__ bq,
                           const float* __restrict__ bk,
                           const float* __restrict__ bv,
                           float* __restrict__ bp)
{
    int idx = blockIdx.x * blockDim.x + threadIdx.x;
    if (idx >= QKVW) return;
    int m = idx / DD;
    int r = idx % DD;
    const float* src = (m == 0) ? bq : (m == 1) ? bk : bv;
    bp[idx] = src[r];
}

// ---------------- bf16x3 tensor-core GEMM (projections) ----------------
#define BM 128
#define BN 64
#define BK 32
#define KP 40

__global__ __launch_bounds__(256)
void gemm_bf16x3(
    int M, int N, int K, float alpha,
    const float* __restrict__ A, long a_bo, long a_bi, int a_rs,
    const float* __restrict__ B, long b_bo, long b_bi, int b_rs, int b_cs,
    float* __restrict__ C, long c_bo, long c_bi, int c_rs,
    const float* __restrict__ bias, int bias_mode, long bias_bo, long bias_bi,
    int z_inner)
{
    const int z  = blockIdx.z;
    const int zo = z / z_inner;
    const int zi = z % z_inner;
    const float* Ab = A + (long)zo * a_bo + (long)zi * a_bi;
    const float* Bb = B + (long)zo * b_bo + (long)zi * b_bi;
    float*       Cb = C + (long)zo * c_bo + (long)zi * c_bi;
    const float* biasb = bias ? bias + (long)zo * bias_bo + (long)zi * bias_bi : nullptr;

    const int m0 = blockIdx.y * BM;
    const int n0 = blockIdx.x * BN;

    __shared__ __nv_bfloat16 Ah[BM][KP], Al[BM][KP];
    __shared__ __nv_bfloat16 Bh[BN][KP], Bl[BN][KP];

    const int tid  = threadIdx.x;
    const int lane = tid & 31;
    const int warp = tid >> 5;
    const int wm = (warp & 3) * 32;
    const int wn = (warp >> 2) * 32;
    const int qr = lane >> 2;
    const int qc = (lane & 3) * 2;

    float acc[2][4][4] = {};

    for (int k0 = 0; k0 < K; k0 += BK) {
        #pragma unroll
        for (int i = 0; i < 4; i++) {
            int e  = tid + i * 256;
            int m  = e >> 3;
            int kq = (e & 7) * 4;
            float4 val = make_float4(0.f, 0.f, 0.f, 0.f);
            if (m0 + m < M)
                val = *(const float4*)(Ab + (long)(m0 + m) * a_rs + k0 + kq);
            float xs[4] = {val.x, val.y, val.z, val.w};
            #pragma unroll
            for (int j = 0; j < 4; j++) {
                __nv_bfloat16 h, l; split_bf16(xs[j], h, l);
                Ah[m][kq + j] = h; Al[m][kq + j] = l;
            }
        }
        if (b_cs == 1) {
            #pragma unroll
            for (int i = 0; i < 8; i++) {
                int e  = tid + i * 256;
                int n  = e & 63;
                int kk = e >> 6;
                float v = Bb[(long)(k0 + kk) * b_rs + (n0 + n)];
                __nv_bfloat16 h, l; split_bf16(v, h, l);
                Bh[n][kk] = h; Bl[n][kk] = l;
            }
        } else {
            #pragma unroll
            for (int i = 0; i < 8; i++) {
                int e  = tid + i * 256;
                int kk = e & 31;
                int n  = e >> 5;
                float v = Bb[(long)(k0 + kk) * b_rs + (long)(n0 + n) * b_cs];
                __nv_bfloat16 h, l; split_bf16(v, h, l);
                Bh[n][kk] = h; Bl[n][kk] = l;
            }
        }
        __syncthreads();

        #pragma unroll
        for (int ks = 0; ks < 2; ks++) {
            const int kc = ks * 16 + qc;
            uint32_t ah[2][4], al[2][4], bh[4][2], bl[4][2];
            #pragma unroll
            for (int mt = 0; mt < 2; mt++) {
                int r0 = wm + mt * 16 + qr;
                ah[mt][0] = lds_u32(&Ah[r0    ][kc    ]);
                ah[mt][1] = lds_u32(&Ah[r0 + 8][kc    ]);
                ah[mt][2] = lds_u32(&Ah[r0    ][kc + 8]);
                ah[mt][3] = lds_u32(&Ah[r0 + 8][kc + 8]);
                al[mt][0] = lds_u32(&Al[r0    ][kc    ]);
                al[mt][1] = lds_u32(&Al[r0 + 8][kc    ]);
                al[mt][2] = lds_u32(&Al[r0    ][kc + 8]);
                al[mt][3] = lds_u32(&Al[r0 + 8][kc + 8]);
            }
            #pragma unroll
            for (int nt = 0; nt < 4; nt++) {
                int nn = wn + nt * 8 + qr;
                bh[nt][0] = lds_u32(&Bh[nn][kc    ]);
                bh[nt][1] = lds_u32(&Bh[nn][kc + 8]);
                bl[nt][0] = lds_u32(&Bl[nn][kc    ]);
                bl[nt][1] = lds_u32(&Bl[nn][kc + 8]);
            }
            #pragma unroll
            for (int mt = 0; mt < 2; mt++)
                #pragma unroll
                for (int nt = 0; nt < 4; nt++) {
                    mma_bf16(acc[mt][nt], ah[mt], bh[nt]);
                    mma_bf16(acc[mt][nt], ah[mt], bl[nt]);
                    mma_bf16(acc[mt][nt], al[mt], bh[nt]);
                }
        }
        __syncthreads();
    }

    #pragma unroll
    for (int mt = 0; mt < 2; mt++) {
        #pragma unroll
        for (int nt = 0; nt < 4; nt++) {
            int r0 = m0 + wm + mt * 16 + qr;
            int r1 = r0 + 8;
            int c  = n0 + wn + nt * 8 + qc;
            float bn0 = 0.f, bn1 = 0.f, bm0 = 0.f, bm1 = 0.f;
            if (bias_mode == 1) { bn0 = biasb[c]; bn1 = biasb[c + 1]; }
            if (r0 < M) {
                if (bias_mode == 2) bm0 = biasb[r0];
                Cb[(long)r0 * c_rs + c    ] = acc[mt][nt][0] * alpha + bn0 + bm0;
                Cb[(long)r0 * c_rs + c + 1] = acc[mt][nt][1] * alpha + bn1 + bm0;
            }
            if (r1 < M) {
                if (bias_mode == 2) bm1 = biasb[r1];
                Cb[(long)r1 * c_rs + c    ] = acc[mt][nt][2] * alpha + bn0 + bm1;
                Cb[(long)r1 * c_rs + c + 1] = acc[mt][nt][3] * alpha + bn1 + bm1;
            }
        }
    }
}

// ---------------- fused flash attention ----------------
// grid (SS/64, BB*HH), 128 threads (4 warps). Warp w owns query rows
// m0 + w*16 .. +15. Loops over 32 chunks of 64 keys.
#define FSC 0.015625f   // 1/HD folded into exp argument
#define VKP 72          // padded smem stride (bf16 elems)

__global__ __launch_bounds__(128)
void flash_attn(const float* __restrict__ qkv, float* __restrict__ comb)
{
    const int z = blockIdx.y;           // b*H + h
    const int b = z >> 3, h = z & 7;
    const int m0 = blockIdx.x * 64;
    const int tid  = threadIdx.x;
    const int lane = tid & 31;
    const int warp = tid >> 5;
    const int qr = lane >> 2;           // 0..7
    const int qc = (lane & 3) * 2;      // 0,2,4,6

    __shared__ __nv_bfloat16 Kh[64][VKP], Kl[64][VKP];
    __shared__ __nv_bfloat16 Vh[64][VKP], Vl[64][VKP];   // transposed: [d][key]

    const float* Qb = qkv + (long)b * SS * QKVW + h * HD;
    const float* Kb = Qb + DD;
    const float* Vb = Qb + 2 * DD;

    // --- load Q fragments once (hi/lo), rows r0 = m0 + warp*16 + qr (+8)
    const int r0 = m0 + warp * 16 + qr;
    uint32_t qh[4][4], ql[4][4];
    #pragma unroll
    for (int ks = 0; ks < 4; ks++) {
        #pragma unroll
        for (int a = 0; a < 4; a++) {
            int row = r0 + (a & 1) * 8;
            int col = ks * 16 + qc + (a >> 1) * 8;
            float2 v = *(const float2*)(Qb + (long)row * QKVW + col);
            __nv_bfloat16 h0, l0, h1, l1;
            split_bf16(v.x, h0, l0); split_bf16(v.y, h1, l1);
            qh[ks][a] = packb(h0, h1);
            ql[ks][a] = packb(l0, l1);
        }
    }

    float o[8][4] = {};
    float m0r = -1e30f, m1r = -1e30f;
    float l0r = 0.f, l1r = 0.f;

    for (int c = 0; c < SS / 64; c++) {
        // --- load K,V chunk into smem (split hi/lo; V transposed)
        #pragma unroll
        for (int i = 0; i < 8; i++) {
            int e   = tid + i * 128;
            int key = e >> 4;
            int d4  = (e & 15) * 4;
            long roff = (long)(c * 64 + key) * QKVW + d4;
            float4 kv = *(const float4*)(Kb + roff);
            float4 vv = *(const float4*)(Vb + roff);
            float xs[4] = {kv.x, kv.y, kv.z, kv.w};
            float ys[4] = {vv.x, vv.y, vv.z, vv.w};
            #pragma unroll
            for (int j = 0; j < 4; j++) {
                __nv_bfloat16 hh, llo;
                split_bf16(xs[j], hh, llo);
                Kh[key][d4 + j] = hh; Kl[key][d4 + j] = llo;
                split_bf16(ys[j], hh, llo);
                Vh[d4 + j][key] = hh; Vl[d4 + j][key] = llo;
            }
        }
        __syncthreads();

        // --- S = Q K^T (raw, scale folded into exp)
        float s[8][4] = {};
        #pragma unroll
        for (int ks = 0; ks < 4; ks++) {
            const int kc = ks * 16 + qc;
            #pragma unroll
            for (int nt = 0; nt < 8; nt++) {
                uint32_t bh[2], bl[2];
                const __nv_bfloat16* ph_ = &Kh[nt * 8 + qr][kc];
                const __nv_bfloat16* pl_ = &Kl[nt * 8 + qr][kc];
                bh[0] = lds_u32(ph_);     bh[1] = lds_u32(ph_ + 8);
                bl[0] = lds_u32(pl_);     bl[1] = lds_u32(pl_ + 8);
                mma_bf16(s[nt], qh[ks], bh);
                mma_bf16(s[nt], ql[ks], bh);
                mma_bf16(s[nt], qh[ks], bl);
            }
        }

        // --- online softmax (rows qr and qr+8 of this warp tile)
        float mx0 = -1e30f, mx1 = -1e30f;
        #pragma unroll
        for (int nt = 0; nt < 8; nt++) {
            mx0 = fmaxf(mx0, fmaxf(s[nt][0], s[nt][1]));
            mx1 = fmaxf(mx1, fmaxf(s[nt][2], s[nt][3]));
        }
        mx0 = fmaxf(mx0, __shfl_xor_sync(0xffffffff, mx0, 1));
        mx0 = fmaxf(mx0, __shfl_xor_sync(0xffffffff, mx0, 2));
        mx1 = fmaxf(mx1, __shfl_xor_sync(0xffffffff, mx1, 1));
        mx1 = fmaxf(mx1, __shfl_xor_sync(0xffffffff, mx1, 2));

        float mn0 = fmaxf(m0r, mx0), mn1 = fmaxf(m1r, mx1);
        float sc0 = __expf((m0r - mn0) * FSC);
        float sc1 = __expf((m1r - mn1) * FSC);
        m0r = mn0; m1r = mn1;

        float sum0 = 0.f, sum1 = 0.f;
        uint32_t ph[4][4], pl[4][4];
        #pragma unroll
        for (int nt = 0; nt < 8; nt++) {
            float p0 = __expf((s[nt][0] - mn0) * FSC);
            float p1 = __expf((s[nt][1] - mn0) * FSC);
            float p2 = __expf((s[nt][2] - mn1) * FSC);
            float p3 = __expf((s[nt][3] - mn1) * FSC);
            sum0 += p0 + p1; sum1 += p2 + p3;
            __nv_bfloat16 h0, lo0, h1, lo1, h2, lo2, h3, lo3;
            split_bf16(p0, h0, lo0); split_bf16(p1, h1, lo1);
            split_bf16(p2, h2, lo2); split_bf16(p3, h3, lo3);
            int ks = nt >> 1, off = (nt & 1) * 2;
            ph[ks][off    ] = packb(h0, h1);
            ph[ks][off + 1] = packb(h2, h3);
            pl[ks][off    ] = packb(lo0, lo1);
            pl[ks][off + 1] = packb(lo2, lo3);
        }
        sum0 += __shfl_xor_sync(0xffffffff, sum0, 1);
        sum0 += __shfl_xor_sync(0xffffffff, sum0, 2);
        sum1 += __shfl_xor_sync(0xffffffff, sum1, 1);
        sum1 += __shfl_xor_sync(0xffffffff, sum1, 2);
        l0r = l0r * sc0 + sum0;
        l1r = l1r * sc1 + sum1;

        #pragma unroll
        for (int nt = 0; nt < 8; nt++) {
            o[nt][0] *= sc0; o[nt][1] *= sc0;
            o[nt][2] *= sc1; o[nt][3] *= sc1;
        }

        // --- O += P V
        #pragma unroll
        for (int ks = 0; ks < 4; ks++) {
            const int kc = ks * 16 + qc;
            #pragma unroll
            for (int nt = 0; nt < 8; nt++) {
                uint32_t bh[2], bl[2];
                const __nv_bfloat16* ph_ = &Vh[nt * 8 + qr][kc];
                const __nv_bfloat16* pl_ = &Vl[nt * 8 + qr][kc];
                bh[0] = lds_u32(ph_);     bh[1] = lds_u32(ph_ + 8);
                bl[0] = lds_u32(pl_);     bl[1] = lds_u32(pl_ + 8);
                mma_bf16(o[nt], ph[ks], bh);
                mma_bf16(o[nt], pl[ks], bh);
                mma_bf16(o[nt], ph[ks], bl);
            }
        }
        __syncthreads();
    }

    // --- epilogue: normalize and write concat layout [B,S,D]
    float inv0 = 1.f / l0r, inv1 = 1.f / l1r;
    float* Cb = comb + (long)b * SS * DD + h * HD;
    #pragma unroll
    for (int nt = 0; nt < 8; nt++) {
        int col = nt * 8 + qc;
        float2 w0 = make_float2(o[nt][0] * inv0, o[nt][1] * inv0);
        float2 w1 = make_float2(o[nt][2] * inv1, o[nt][3] * inv1);
        *(float2*)(Cb + (long)r0 * DD + col)       = w0;
        *(float2*)(Cb + (long)(r0 + 8) * DD + col) = w1;
    }
}

// ---------------- launch ----------------
extern "C" void kernel_launch(void* const* d_in, const int* in_sizes, int n_in,
                              void* d_out, int out_size)
{
    (void)in_sizes; (void)n_in; (void)out_size;
    const float* x  = (const float*)d_in[0];
    const float* Wq = (const float*)d_in[1];
    const float* bq = (const float*)d_in[2];
    const float* Wk = (const float*)d_in[3];
    const float* bk = (const float*)d_in[4];
    const float* Wv = (const float*)d_in[5];
    const float* bv = (const float*)d_in[6];
    const float* Wt = (const float*)d_in[7];
    const float* bt = (const float*)d_in[8];
    const float* Wo = (const float*)d_in[9];
    const float* bo = (const float*)d_in[10];
    float* out = (float*)d_out;

    float *qkv, *comb, *up, *wp, *bp;
    cudaGetSymbolAddress((void**)&qkv,  g_qkv);
    cudaGetSymbolAddress((void**)&comb, g_comb);
    cudaGetSymbolAddress((void**)&up,   g_up);
    cudaGetSymbolAddress((void**)&wp,   g_wp);
    cudaGetSymbolAddress((void**)&bp,   g_bp);

    dim3 blk(256);

    // 0) pack QKV weights/bias into [I, 3*D] / [3*D]
    pack_qkv_w<<<(3 * II * DD + 255) / 256, 256>>>(Wq, Wk, Wv, wp);
    pack_qkv_b<<<(QKVW + 255) / 256, 256>>>(bq, bk, bv, bp);

    // 1) fused QKV: [8192,512] @ [512,1536] -> qkv
    {
        dim3 grid(QKVW / BN, NT / BM, 1);
        gemm_bf16x3<<<grid, blk>>>(NT, QKVW, II, 1.f,
            x,   0, 0, II,
            wp,  0, 0, QKVW, 1,
            qkv, 0, 0, QKVW,
            bp, 1, 0, 0, 1);
    }

    // 2) fused attention (scores + softmax + ctx) -> comb [B,S,D]
    {
        dim3 grid(SS / 64, BB * HH);
        flash_attn<<<grid, 128>>>(qkv, comb);
    }

    // 3) up[b,p,d] = sum_s Wt[p,s] * comb[b,s,d] + bt[p]
    {
        dim3 grid(DD / BN, (PP + BM - 1) / BM, BB);
        gemm_bf16x3<<<grid, blk>>>(PP, DD, SS, 1.f,
            Wt,   0, 0, SS,
            comb, (long)SS * DD, 0, DD, 1,
            up,   (long)PP * DD, 0, DD,
            bt, 2, 0, 0, 1);
    }

    // 4) out[b,p,o] = sum_d up[b,p,d] * Wo[o,d] + bo[o]
    {
        dim3 grid(II / BN, (PP + BM - 1) / BM, BB);
        gemm_bf16x3<<<grid, blk>>>(PP, II, DD, 1.f,
            up, (long)PP * DD, 0, DD,
            Wo, 0, 0, 1, DD,
            out, (long)PP * II, 0, II,
            bo, 1, 0, 0, 1);
    }
}

// round 4
// speedup vs baseline: 2.2243x; 1.0726x over previous
#include <cuda_runtime.h>
#include <cuda_bf16.h>
#include <math.h>
#include <stdint.h>

// Problem dims
#define BB 4
#define SS 2048
#define II 512
#define DD 512
#define HH 8
#define HD 64
#define PP 720
#define NT (BB*SS)        // 8192 tokens
#define QKVW (3*DD)       // 1536

// ---------------- scratch (__device__ globals, no allocation) ----------------
__device__ __nv_bfloat16 g_qkvh[(size_t)NT * QKVW];    // qkv hi plane
__device__ __nv_bfloat16 g_qkvl[(size_t)NT * QKVW];    // qkv lo plane
__device__ float g_comb[(size_t)NT * DD];              // [B,S,D]
__device__ float g_up[(size_t)BB * PP * DD];           // [B,P,D]
__device__ float g_wp[(size_t)II * QKVW];              // packed QKV weights [I, 3*D]
__device__ float g_bp[QKVW];                           // packed QKV bias

// ---------------- helpers ----------------
__device__ __forceinline__ uint32_t lds_u32(const __nv_bfloat16* p) {
    return *(const uint32_t*)p;
}
__device__ __forceinline__ void mma_bf16(float* c, const uint32_t* a, const uint32_t* b) {
    asm volatile(
        "mma.sync.aligned.m16n8k16.row.col.f32.bf16.bf16.f32 "
        "{%0,%1,%2,%3}, {%4,%5,%6,%7}, {%8,%9}, {%0,%1,%2,%3};\n"
        : "+f"(c[0]), "+f"(c[1]), "+f"(c[2]), "+f"(c[3])
        : "r"(a[0]), "r"(a[1]), "r"(a[2]), "r"(a[3]), "r"(b[0]), "r"(b[1]));
}
__device__ __forceinline__ void split_bf16(float x, __nv_bfloat16& h, __nv_bfloat16& l) {
    h = __float2bfloat16(x);
    l = __float2bfloat16(x - __bfloat162float(h));
}
__device__ __forceinline__ uint32_t packb(__nv_bfloat16 a, __nv_bfloat16 b) {
    __nv_bfloat162 t; t.x = a; t.y = b;
    return *(uint32_t*)&t;
}
__device__ __forceinline__ void ldsm4(uint32_t* r, const __nv_bfloat16* p) {
    uint32_t a = (uint32_t)__cvta_generic_to_shared(p);
    asm volatile("ldmatrix.sync.aligned.m8n8.x4.shared.b16 {%0,%1,%2,%3}, [%4];\n"
        : "=r"(r[0]), "=r"(r[1]), "=r"(r[2]), "=r"(r[3]) : "r"(a));
}
__device__ __forceinline__ void ldsm4t(uint32_t* r, const __nv_bfloat16* p) {
    uint32_t a = (uint32_t)__cvta_generic_to_shared(p);
    asm volatile("ldmatrix.sync.aligned.m8n8.x4.trans.shared.b16 {%0,%1,%2,%3}, [%4];\n"
        : "=r"(r[0]), "=r"(r[1]), "=r"(r[2]), "=r"(r[3]) : "r"(a));
}
__device__ __forceinline__ void cp16(__nv_bfloat16* dst, const __nv_bfloat16* src) {
    uint32_t d = (uint32_t)__cvta_generic_to_shared(dst);
    asm volatile("cp.async.cg.shared.global [%0], [%1], 16;\n" :: "r"(d), "l"(src));
}
#define CP_COMMIT() asm volatile("cp.async.commit_group;\n")
#define CP_WAIT0()  asm volatile("cp.async.wait_group 0;\n")

// ---------------- weight packing ----------------
__global__ void pack_qkv_w(const float* __restrict__ Wq,
                           const float* __restrict__ Wk,
                           const float* __restrict__ Wv,
                           float* __restrict__ Wp)
{
    int idx = blockIdx.x * blockDim.x + threadIdx.x;
    if (idx >= 3 * II * DD) return;
    int m   = idx / (II * DD);
    int rem = idx % (II * DD);          // = h*(512*64) + i*64 + d
    int h   = rem / (II * HD);
    int i   = (rem / HD) % II;
    int d   = rem % HD;
    const float* src = (m == 0) ? Wq : (m == 1) ? Wk : Wv;
    Wp[(long)i * QKVW + m * DD + h * HD + d] = src[rem];
}

__global__ void pack_qkv_b(const float* __restrict__ bq,
                           const float* __restrict__ bk,
                           const float* __restrict__ bv,
                           float* __restrict__ bp)
{
    int idx = blockIdx.x * blockDim.x + threadIdx.x;
    if (idx >= QKVW) return;
    int m = idx / DD;
    int r = idx % DD;
    const float* src = (m == 0) ? bq : (m == 1) ? bk : bv;
    bp[idx] = src[r];
}

// ---------------- bf16x3 tensor-core GEMM (projections) ----------------
// If Ch != nullptr, the result (+bias) is written as split bf16 hi/lo planes
// instead of fp32 C.
#define BM 128
#define BN 64
#define BK 32
#define KP 40

__global__ __launch_bounds__(256)
void gemm_bf16x3(
    int M, int N, int K, float alpha,
    const float* __restrict__ A, long a_bo, long a_bi, int a_rs,
    const float* __restrict__ B, long b_bo, long b_bi, int b_rs, int b_cs,
    float* __restrict__ C, long c_bo, long c_bi, int c_rs,
    __nv_bfloat16* __restrict__ Ch, __nv_bfloat16* __restrict__ Cl,
    const float* __restrict__ bias, int bias_mode, long bias_bo, long bias_bi,
    int z_inner)
{
    const int z  = blockIdx.z;
    const int zo = z / z_inner;
    const int zi = z % z_inner;
    const float* Ab = A + (long)zo * a_bo + (long)zi * a_bi;
    const float* Bb = B + (long)zo * b_bo + (long)zi * b_bi;
    float*       Cb = C + (long)zo * c_bo + (long)zi * c_bi;
    const float* biasb = bias ? bias + (long)zo * bias_bo + (long)zi * bias_bi : nullptr;

    const int m0 = blockIdx.y * BM;
    const int n0 = blockIdx.x * BN;

    __shared__ __nv_bfloat16 Ah[BM][KP], Al[BM][KP];
    __shared__ __nv_bfloat16 Bh[BN][KP], Bl[BN][KP];

    const int tid  = threadIdx.x;
    const int lane = tid & 31;
    const int warp = tid >> 5;
    const int wm = (warp & 3) * 32;
    const int wn = (warp >> 2) * 32;
    const int qr = lane >> 2;
    const int qc = (lane & 3) * 2;

    float acc[2][4][4] = {};

    for (int k0 = 0; k0 < K; k0 += BK) {
        #pragma unroll
        for (int i = 0; i < 4; i++) {
            int e  = tid + i * 256;
            int m  = e >> 3;
            int kq = (e & 7) * 4;
            float4 val = make_float4(0.f, 0.f, 0.f, 0.f);
            if (m0 + m < M)
                val = *(const float4*)(Ab + (long)(m0 + m) * a_rs + k0 + kq);
            float xs[4] = {val.x, val.y, val.z, val.w};
            #pragma unroll
            for (int j = 0; j < 4; j++) {
                __nv_bfloat16 h, l; split_bf16(xs[j], h, l);
                Ah[m][kq + j] = h; Al[m][kq + j] = l;
            }
        }
        if (b_cs == 1) {
            #pragma unroll
            for (int i = 0; i < 8; i++) {
                int e  = tid + i * 256;
                int n  = e & 63;
                int kk = e >> 6;
                float v = Bb[(long)(k0 + kk) * b_rs + (n0 + n)];
                __nv_bfloat16 h, l; split_bf16(v, h, l);
                Bh[n][kk] = h; Bl[n][kk] = l;
            }
        } else {
            #pragma unroll
            for (int i = 0; i < 8; i++) {
                int e  = tid + i * 256;
                int kk = e & 31;
                int n  = e >> 5;
                float v = Bb[(long)(k0 + kk) * b_rs + (long)(n0 + n) * b_cs];
                __nv_bfloat16 h, l; split_bf16(v, h, l);
                Bh[n][kk] = h; Bl[n][kk] = l;
            }
        }
        __syncthreads();

        #pragma unroll
        for (int ks = 0; ks < 2; ks++) {
            const int kc = ks * 16 + qc;
            uint32_t ah[2][4], al[2][4], bh[4][2], bl[4][2];
            #pragma unroll
            for (int mt = 0; mt < 2; mt++) {
                int r0 = wm + mt * 16 + qr;
                ah[mt][0] = lds_u32(&Ah[r0    ][kc    ]);
                ah[mt][1] = lds_u32(&Ah[r0 + 8][kc    ]);
                ah[mt][2] = lds_u32(&Ah[r0    ][kc + 8]);
                ah[mt][3] = lds_u32(&Ah[r0 + 8][kc + 8]);
                al[mt][0] = lds_u32(&Al[r0    ][kc    ]);
                al[mt][1] = lds_u32(&Al[r0 + 8][kc    ]);
                al[mt][2] = lds_u32(&Al[r0    ][kc + 8]);
                al[mt][3] = lds_u32(&Al[r0 + 8][kc + 8]);
            }
            #pragma unroll
            for (int nt = 0; nt < 4; nt++) {
                int nn = wn + nt * 8 + qr;
                bh[nt][0] = lds_u32(&Bh[nn][kc    ]);
                bh[nt][1] = lds_u32(&Bh[nn][kc + 8]);
                bl[nt][0] = lds_u32(&Bl[nn][kc    ]);
                bl[nt][1] = lds_u32(&Bl[nn][kc + 8]);
            }
            #pragma unroll
            for (int mt = 0; mt < 2; mt++)
                #pragma unroll
                for (int nt = 0; nt < 4; nt++) {
                    mma_bf16(acc[mt][nt], ah[mt], bh[nt]);
                    mma_bf16(acc[mt][nt], ah[mt], bl[nt]);
                    mma_bf16(acc[mt][nt], al[mt], bh[nt]);
                }
        }
        __syncthreads();
    }

    #pragma unroll
    for (int mt = 0; mt < 2; mt++) {
        #pragma unroll
        for (int nt = 0; nt < 4; nt++) {
            int r0 = m0 + wm + mt * 16 + qr;
            int r1 = r0 + 8;
            int c  = n0 + wn + nt * 8 + qc;
            float bn0 = 0.f, bn1 = 0.f;
            if (bias_mode == 1) { bn0 = biasb[c]; bn1 = biasb[c + 1]; }
            float v00 = acc[mt][nt][0] * alpha + bn0;
            float v01 = acc[mt][nt][1] * alpha + bn1;
            float v10 = acc[mt][nt][2] * alpha + bn0;
            float v11 = acc[mt][nt][3] * alpha + bn1;
            if (bias_mode == 2) {
                if (r0 < M) { float bm = biasb[r0]; v00 += bm; v01 += bm; }
                if (r1 < M) { float bm = biasb[r1]; v10 += bm; v11 += bm; }
            }
            if (Ch) {
                __nv_bfloat16 h0, l0, h1, l1;
                if (r0 < M) {
                    split_bf16(v00, h0, l0); split_bf16(v01, h1, l1);
                    *(uint32_t*)(Ch + (long)r0 * c_rs + c) = packb(h0, h1);
                    *(uint32_t*)(Cl + (long)r0 * c_rs + c) = packb(l0, l1);
                }
                if (r1 < M) {
                    split_bf16(v10, h0, l0); split_bf16(v11, h1, l1);
                    *(uint32_t*)(Ch + (long)r1 * c_rs + c) = packb(h0, h1);
                    *(uint32_t*)(Cl + (long)r1 * c_rs + c) = packb(l0, l1);
                }
            } else {
                if (r0 < M) {
                    Cb[(long)r0 * c_rs + c    ] = v00;
                    Cb[(long)r0 * c_rs + c + 1] = v01;
                }
                if (r1 < M) {
                    Cb[(long)r1 * c_rs + c    ] = v10;
                    Cb[(long)r1 * c_rs + c + 1] = v11;
                }
            }
        }
    }
}

// ---------------- fused flash attention (bf16 planes, cp.async, ldmatrix) ----------------
#define FSC 0.015625f   // 1/HD folded into exp argument
#define VKP 72          // padded smem row stride (bf16 elems); 144B -> ldmatrix conflict-free
#define FTILE (64*VKP)  // elems per 64x64 tile
#define FSMEM (2*4*FTILE*2)  // bytes: 2 buffers x {Kh,Kl,Vh,Vl}

__device__ __forceinline__ void flash_load_chunk(
    __nv_bfloat16* buf,
    const __nv_bfloat16* __restrict__ qh_plane,
    const __nv_bfloat16* __restrict__ ql_plane,
    long kbase, long vbase, int c, int tid)
{
    #pragma unroll
    for (int i = 0; i < 16; i++) {
        int e    = tid + i * 128;
        int tile = e >> 9;            // 0=Kh 1=Kl 2=Vh 3=Vl
        int rem  = e & 511;
        int row  = rem >> 3;
        int seg  = rem & 7;
        const __nv_bfloat16* plane = (tile & 1) ? ql_plane : qh_plane;
        long off = ((tile < 2) ? kbase : vbase) + (long)(c * 64 + row) * QKVW + seg * 8;
        cp16(buf + tile * FTILE + row * VKP + seg * 8, plane + off);
    }
}

__global__ __launch_bounds__(128)
void flash_attn(const __nv_bfloat16* __restrict__ qh_plane,
                const __nv_bfloat16* __restrict__ ql_plane,
                float* __restrict__ comb)
{
    extern __shared__ __align__(16) __nv_bfloat16 sm[];
    const int z = blockIdx.y;           // b*H + h
    const int b = z >> 3, h = z & 7;
    const int m0 = blockIdx.x * 64;
    const int tid  = threadIdx.x;
    const int lane = tid & 31;
    const int warp = tid >> 5;
    const int qr = lane >> 2;
    const int qc = (lane & 3) * 2;

    const long zbase = (long)b * SS * QKVW + h * HD;
    const long kbase = zbase + DD;
    const long vbase = zbase + 2 * DD;

    // --- load Q fragments once from bf16 planes
    const int r0 = m0 + warp * 16 + qr;
    uint32_t qh[4][4], ql[4][4];
    #pragma unroll
    for (int ks = 0; ks < 4; ks++) {
        #pragma unroll
        for (int a = 0; a < 4; a++) {
            int row = r0 + (a & 1) * 8;
            int col = ks * 16 + qc + (a >> 1) * 8;
            long off = zbase + (long)row * QKVW + col;
            qh[ks][a] = *(const uint32_t*)(qh_plane + off);
            ql[ks][a] = *(const uint32_t*)(ql_plane + off);
        }
    }

    float o[8][4] = {};
    float m0r = -1e30f, m1r = -1e30f;
    float l0r = 0.f, l1r = 0.f;

    // ldmatrix per-lane offsets
    const int skey_off = ((lane >> 4) & 1) * 8 + (lane & 7);  // within 16-key group (S)
    const int scol_off = ((lane >> 3) & 1) * 8;               // d offset (S)
    const int vkey_off = ((lane >> 3) & 1) * 8 + (lane & 7);  // within 16-key group (PV)
    const int vcol_off = ((lane >> 4) & 1) * 8;               // d offset (PV)

    flash_load_chunk(sm, qh_plane, ql_plane, kbase, vbase, 0, tid);
    CP_COMMIT();

    for (int c = 0; c < SS / 64; c++) {
        CP_WAIT0();
        __syncthreads();
        if (c + 1 < SS / 64) {
            flash_load_chunk(sm + ((c + 1) & 1) * 4 * FTILE,
                             qh_plane, ql_plane, kbase, vbase, c + 1, tid);
            CP_COMMIT();
        }
        const __nv_bfloat16* Kh_ = sm + (c & 1) * 4 * FTILE;
        const __nv_bfloat16* Kl_ = Kh_ + FTILE;
        const __nv_bfloat16* Vh_ = Kh_ + 2 * FTILE;
        const __nv_bfloat16* Vl_ = Kh_ + 3 * FTILE;

        // --- S = Q K^T
        float s[8][4] = {};
        #pragma unroll
        for (int ks = 0; ks < 4; ks++) {
            const int kc = ks * 16;
            #pragma unroll
            for (int ntp = 0; ntp < 4; ntp++) {
                const __nv_bfloat16* base = Kh_ + (ntp * 16 + skey_off) * VKP + kc + scol_off;
                uint32_t bh[4], bl[4];
                ldsm4(bh, base);
                ldsm4(bl, base + FTILE);   // Kl_ is FTILE after Kh_
                mma_bf16(s[2 * ntp    ], qh[ks], bh);
                mma_bf16(s[2 * ntp    ], ql[ks], bh);
                mma_bf16(s[2 * ntp    ], qh[ks], bl);
                mma_bf16(s[2 * ntp + 1], qh[ks], bh + 2);
                mma_bf16(s[2 * ntp + 1], ql[ks], bh + 2);
                mma_bf16(s[2 * ntp + 1], qh[ks], bl + 2);
            }
        }

        // --- online softmax
        float mx0 = -1e30f, mx1 = -1e30f;
        #pragma unroll
        for (int nt = 0; nt < 8; nt++) {
            mx0 = fmaxf(mx0, fmaxf(s[nt][0], s[nt][1]));
            mx1 = fmaxf(mx1, fmaxf(s[nt][2], s[nt][3]));
        }
        mx0 = fmaxf(mx0, __shfl_xor_sync(0xffffffff, mx0, 1));
        mx0 = fmaxf(mx0, __shfl_xor_sync(0xffffffff, mx0, 2));
        mx1 = fmaxf(mx1, __shfl_xor_sync(0xffffffff, mx1, 1));
        mx1 = fmaxf(mx1, __shfl_xor_sync(0xffffffff, mx1, 2));

        float mn0 = fmaxf(m0r, mx0), mn1 = fmaxf(m1r, mx1);
        float sc0 = __expf((m0r - mn0) * FSC);
        float sc1 = __expf((m1r - mn1) * FSC);
        m0r = mn0; m1r = mn1;

        float sum0 = 0.f, sum1 = 0.f;
        uint32_t ph[4][4], pl[4][4];
        #pragma unroll
        for (int nt = 0; nt < 8; nt++) {
            float p0 = __expf((s[nt][0] - mn0) * FSC);
            float p1 = __expf((s[nt][1] - mn0) * FSC);
            float p2 = __expf((s[nt][2] - mn1) * FSC);
            float p3 = __expf((s[nt][3] - mn1) * FSC);
            sum0 += p0 + p1; sum1 += p2 + p3;
            __nv_bfloat16 h0, lo0, h1, lo1, h2, lo2, h3, lo3;
            split_bf16(p0, h0, lo0); split_bf16(p1, h1, lo1);
            split_bf16(p2, h2, lo2); split_bf16(p3, h3, lo3);
            int ks = nt >> 1, off = (nt & 1) * 2;
            ph[ks][off    ] = packb(h0, h1);
            ph[ks][off + 1] = packb(h2, h3);
            pl[ks][off    ] = packb(lo0, lo1);
            pl[ks][off + 1] = packb(lo2, lo3);
        }
        sum0 += __shfl_xor_sync(0xffffffff, sum0, 1);
        sum0 += __shfl_xor_sync(0xffffffff, sum0, 2);
        sum1 += __shfl_xor_sync(0xffffffff, sum1, 1);
        sum1 += __shfl_xor_sync(0xffffffff, sum1, 2);
        l0r = l0r * sc0 + sum0;
        l1r = l1r * sc1 + sum1;

        #pragma unroll
        for (int nt = 0; nt < 8; nt++) {
            o[nt][0] *= sc0; o[nt][1] *= sc0;
            o[nt][2] *= sc1; o[nt][3] *= sc1;
        }

        // --- O += P V   (V in [key][d] layout, trans ldmatrix)
        #pragma unroll
        for (int ks = 0; ks < 4; ks++) {
            const int kc = ks * 16;
            #pragma unroll
            for (int ntp = 0; ntp < 4; ntp++) {
                const __nv_bfloat16* base = Vh_ + (kc + vkey_off) * VKP + ntp * 16 + vcol_off;
                uint32_t vh4[4], vl4[4];
                ldsm4t(vh4, base);
                ldsm4t(vl4, base + FTILE);  // Vl_ is FTILE after Vh_
                mma_bf16(o[2 * ntp    ], ph[ks], vh4);
                mma_bf16(o[2 * ntp    ], pl[ks], vh4);
                mma_bf16(o[2 * ntp    ], ph[ks], vl4);
                mma_bf16(o[2 * ntp + 1], ph[ks], vh4 + 2);
                mma_bf16(o[2 * ntp + 1], pl[ks], vh4 + 2);
                mma_bf16(o[2 * ntp + 1], ph[ks], vl4 + 2);
            }
        }
        __syncthreads();
    }

    // --- epilogue: normalize and write concat layout [B,S,D]
    float inv0 = 1.f / l0r, inv1 = 1.f / l1r;
    float* Cb = comb + (long)b * SS * DD + h * HD;
    #pragma unroll
    for (int nt = 0; nt < 8; nt++) {
        int col = nt * 8 + qc;
        float2 w0 = make_float2(o[nt][0] * inv0, o[nt][1] * inv0);
        float2 w1 = make_float2(o[nt][2] * inv1, o[nt][3] * inv1);
        *(float2*)(Cb + (long)r0 * DD + col)       = w0;
        *(float2*)(Cb + (long)(r0 + 8) * DD + col) = w1;
    }
}

// ---------------- launch ----------------
extern "C" void kernel_launch(void* const* d_in, const int* in_sizes, int n_in,
                              void* d_out, int out_size)
{
    (void)in_sizes; (void)n_in; (void)out_size;
    const float* x  = (const float*)d_in[0];
    const float* Wq = (const float*)d_in[1];
    const float* bq = (const float*)d_in[2];
    const float* Wk = (const float*)d_in[3];
    const float* bk = (const float*)d_in[4];
    const float* Wv = (const float*)d_in[5];
    const float* bv = (const float*)d_in[6];
    const float* Wt = (const float*)d_in[7];
    const float* bt = (const float*)d_in[8];
    const float* Wo = (const float*)d_in[9];
    const float* bo = (const float*)d_in[10];
    float* out = (float*)d_out;

    __nv_bfloat16 *qkvh, *qkvl;
    float *comb, *up, *wp, *bp;
    cudaGetSymbolAddress((void**)&qkvh, g_qkvh);
    cudaGetSymbolAddress((void**)&qkvl, g_qkvl);
    cudaGetSymbolAddress((void**)&comb, g_comb);
    cudaGetSymbolAddress((void**)&up,   g_up);
    cudaGetSymbolAddress((void**)&wp,   g_wp);
    cudaGetSymbolAddress((void**)&bp,   g_bp);

    static bool attr_set = false;
    if (!attr_set) {
        cudaFuncSetAttribute(flash_attn,
            cudaFuncAttributeMaxDynamicSharedMemorySize, FSMEM);
        attr_set = true;
    }

    dim3 blk(256);

    // 0) pack QKV weights/bias into [I, 3*D] / [3*D]
    pack_qkv_w<<<(3 * II * DD + 255) / 256, 256>>>(Wq, Wk, Wv, wp);
    pack_qkv_b<<<(QKVW + 255) / 256, 256>>>(bq, bk, bv, bp);

    // 1) fused QKV: [8192,512] @ [512,1536] -> bf16 hi/lo planes
    {
        dim3 grid(QKVW / BN, NT / BM, 1);
        gemm_bf16x3<<<grid, blk>>>(NT, QKVW, II, 1.f,
            x,   0, 0, II,
            wp,  0, 0, QKVW, 1,
            nullptr, 0, 0, QKVW,
            qkvh, qkvl,
            bp, 1, 0, 0, 1);
    }

    // 2) fused attention (scores + softmax + ctx) -> comb [B,S,D]
    {
        dim3 grid(SS / 64, BB * HH);
        flash_attn<<<grid, 128, FSMEM>>>(qkvh, qkvl, comb);
    }

    // 3) up[b,p,d] = sum_s Wt[p,s] * comb[b,s,d] + bt[p]
    {
        dim3 grid(DD / BN, (PP + BM - 1) / BM, BB);
        gemm_bf16x3<<<grid, blk>>>(PP, DD, SS, 1.f,
            Wt,   0, 0, SS,
            comb, (long)SS * DD, 0, DD, 1,
            up,   (long)PP * DD, 0, DD,
            nullptr, nullptr,
            bt, 2, 0, 0, 1);
    }

    // 4) out[b,p,o] = sum_d up[b,p,d] * Wo[o,d] + bo[o]
    {
        dim3 grid(II / BN, (PP + BM - 1) / BM, BB);
        gemm_bf16x3<<<grid, blk>>>(PP, II, DD, 1.f,
            up, (long)PP * DD, 0, DD,
            Wo, 0, 0, 1, DD,
            out, (long)PP * II, 0, II,
            nullptr, nullptr,
            bo, 1, 0, 0, 1);
    }
}

// round 5
// speedup vs baseline: 4.6243x; 2.0790x over previous
#include <cuda_runtime.h>
#include <cuda_bf16.h>
#include <math.h>
#include <stdint.h>

// Problem dims
#define BB 4
#define SS 2048
#define II 512
#define DD 512
#define HH 8
#define HD 64
#define PP 720
#define NT (BB*SS)        // 8192 tokens
#define QKVW (3*DD)       // 1536

// ---------------- scratch (__device__ globals, no allocation) ----------------
__device__ __nv_bfloat16 g_qkvh[(size_t)NT * QKVW];
__device__ __nv_bfloat16 g_qkvl[(size_t)NT * QKVW];
__device__ __nv_bfloat16 g_combh[(size_t)NT * DD];
__device__ __nv_bfloat16 g_combl[(size_t)NT * DD];
__device__ __nv_bfloat16 g_uph[(size_t)BB * PP * DD];
__device__ __nv_bfloat16 g_upl[(size_t)BB * PP * DD];
__device__ __nv_bfloat16 g_xh[(size_t)NT * II];
__device__ __nv_bfloat16 g_xl[(size_t)NT * II];
__device__ __nv_bfloat16 g_wph[(size_t)II * QKVW];
__device__ __nv_bfloat16 g_wpl[(size_t)II * QKVW];
__device__ __nv_bfloat16 g_wth[(size_t)PP * SS];
__device__ __nv_bfloat16 g_wtl[(size_t)PP * SS];
__device__ __nv_bfloat16 g_woh[(size_t)DD * II];   // transposed: [d][o]
__device__ __nv_bfloat16 g_wol[(size_t)DD * II];
__device__ float g_bp[QKVW];

// ---------------- helpers ----------------
__device__ __forceinline__ void mma_bf16(float* c, const uint32_t* a, const uint32_t* b) {
    asm volatile(
        "mma.sync.aligned.m16n8k16.row.col.f32.bf16.bf16.f32 "
        "{%0,%1,%2,%3}, {%4,%5,%6,%7}, {%8,%9}, {%0,%1,%2,%3};\n"
        : "+f"(c[0]), "+f"(c[1]), "+f"(c[2]), "+f"(c[3])
        : "r"(a[0]), "r"(a[1]), "r"(a[2]), "r"(a[3]), "r"(b[0]), "r"(b[1]));
}
__device__ __forceinline__ void split_bf16(float x, __nv_bfloat16& h, __nv_bfloat16& l) {
    h = __float2bfloat16(x);
    l = __float2bfloat16(x - __bfloat162float(h));
}
__device__ __forceinline__ uint32_t packb(__nv_bfloat16 a, __nv_bfloat16 b) {
    __nv_bfloat162 t; t.x = a; t.y = b;
    return *(uint32_t*)&t;
}
__device__ __forceinline__ void ldsm4(uint32_t* r, const __nv_bfloat16* p) {
    uint32_t a = (uint32_t)__cvta_generic_to_shared(p);
    asm volatile("ldmatrix.sync.aligned.m8n8.x4.shared.b16 {%0,%1,%2,%3}, [%4];\n"
        : "=r"(r[0]), "=r"(r[1]), "=r"(r[2]), "=r"(r[3]) : "r"(a));
}
__device__ __forceinline__ void ldsm4t(uint32_t* r, const __nv_bfloat16* p) {
    uint32_t a = (uint32_t)__cvta_generic_to_shared(p);
    asm volatile("ldmatrix.sync.aligned.m8n8.x4.trans.shared.b16 {%0,%1,%2,%3}, [%4];\n"
        : "=r"(r[0]), "=r"(r[1]), "=r"(r[2]), "=r"(r[3]) : "r"(a));
}
__device__ __forceinline__ void cp16(__nv_bfloat16* dst, const __nv_bfloat16* src) {
    uint32_t d = (uint32_t)__cvta_generic_to_shared(dst);
    asm volatile("cp.async.cg.shared.global [%0], [%1], 16;\n" :: "r"(d), "l"(src));
}
#define CP_COMMIT() asm volatile("cp.async.commit_group;\n")
#define CP_WAIT0()  asm volatile("cp.async.wait_group 0;\n")

// ---------------- pack kernels (fp32 -> bf16 hi/lo planes) ----------------
__global__ void pack_split(const float* __restrict__ src,
                           __nv_bfloat16* __restrict__ dh,
                           __nv_bfloat16* __restrict__ dl, int n)
{
    int i = blockIdx.x * blockDim.x + threadIdx.x;
    if (i >= n) return;
    __nv_bfloat16 h, l; split_bf16(src[i], h, l);
    dh[i] = h; dl[i] = l;
}

__global__ void pack_qkv_w(const float* __restrict__ Wq,
                           const float* __restrict__ Wk,
                           const float* __restrict__ Wv,
                           __nv_bfloat16* __restrict__ dh,
                           __nv_bfloat16* __restrict__ dl)
{
    int idx = blockIdx.x * blockDim.x + threadIdx.x;
    if (idx >= 3 * II * DD) return;
    int m   = idx / (II * DD);
    int rem = idx % (II * DD);          // = h*(512*64) + i*64 + d
    int h   = rem / (II * HD);
    int i   = (rem / HD) % II;
    int d   = rem % HD;
    const float* src = (m == 0) ? Wq : (m == 1) ? Wk : Wv;
    __nv_bfloat16 hi, lo; split_bf16(src[rem], hi, lo);
    long o = (long)i * QKVW + m * DD + h * HD + d;
    dh[o] = hi; dl[o] = lo;
}

__global__ void pack_wo_t(const float* __restrict__ Wo,
                          __nv_bfloat16* __restrict__ dh,
                          __nv_bfloat16* __restrict__ dl)
{
    int idx = blockIdx.x * blockDim.x + threadIdx.x;  // o*DD + d
    if (idx >= II * DD) return;
    int o = idx / DD, d = idx % DD;
    __nv_bfloat16 hi, lo; split_bf16(Wo[idx], hi, lo);
    dh[d * II + o] = hi; dl[d * II + o] = lo;
}

__global__ void pack_qkv_b(const float* __restrict__ bq,
                           const float* __restrict__ bk,
                           const float* __restrict__ bv,
                           float* __restrict__ bp)
{
    int idx = blockIdx.x * blockDim.x + threadIdx.x;
    if (idx >= QKVW) return;
    int m = idx / DD;
    int r = idx % DD;
    const float* src = (m == 0) ? bq : (m == 1) ? bk : bv;
    bp[idx] = src[r];
}

// ---------------- bf16-plane tensor-core GEMM ----------------
// C = A @ B (+bias). A planes [m][k] k-contiguous (ld=lda); B planes [k][n]
// n-contiguous (ld=ldb). Output either fp32 C or bf16 planes Ch/Cl.
// bias_mode: 0 none, 1 per-n, 2 per-m. Batched over blockIdx.z.
#define GBM 128
#define GBN 64
#define GBK 32
#define ASTR 40
#define BSTR 72
#define A_TILE (GBM*ASTR)              // 5120 elems per plane
#define B_TILE (GBK*BSTR)              // 2304
#define STAGE (2*A_TILE + 2*B_TILE)    // 14848 elems
#define GSMEM (2*STAGE*2)              // 59392 bytes

__device__ __forceinline__ void gemm_load_stage(
    __nv_bfloat16* buf,
    const __nv_bfloat16* __restrict__ Ah, const __nv_bfloat16* __restrict__ Al,
    long a_off, int lda, int M, int m0,
    const __nv_bfloat16* __restrict__ Bh, const __nv_bfloat16* __restrict__ Bl,
    long b_off, int ldb, int n0, int k0, int tid)
{
    #pragma unroll
    for (int i = 0; i < 4; i++) {
        int e = tid + i * 256;
        int plane = e >> 9;
        int rem = e & 511;
        int m = rem >> 2;
        int seg = rem & 3;
        int mg = m0 + m; if (mg >= M) mg = M - 1;
        const __nv_bfloat16* src = (plane ? Al : Ah) + a_off + (long)mg * lda + k0 + seg * 8;
        cp16(buf + plane * A_TILE + m * ASTR + seg * 8, src);
    }
    #pragma unroll
    for (int i = 0; i < 2; i++) {
        int e = tid + i * 256;
        int plane = e >> 8;
        int rem = e & 255;
        int k = rem >> 3;
        int seg = rem & 7;
        const __nv_bfloat16* src = (plane ? Bl : Bh) + b_off + (long)(k0 + k) * ldb + n0 + seg * 8;
        cp16(buf + 2 * A_TILE + plane * B_TILE + k * BSTR + seg * 8, src);
    }
}

__global__ __launch_bounds__(256)
void gemm_planes(
    int M, int N, int K,
    const __nv_bfloat16* __restrict__ Ah, const __nv_bfloat16* __restrict__ Al,
    long a_b, int lda,
    const __nv_bfloat16* __restrict__ Bh, const __nv_bfloat16* __restrict__ Bl,
    long b_b, int ldb,
    float* __restrict__ C, __nv_bfloat16* __restrict__ Ch, __nv_bfloat16* __restrict__ Cl,
    long c_b, int ldc,
    const float* __restrict__ bias, int bias_mode)
{
    extern __shared__ __align__(16) __nv_bfloat16 gsm[];
    const int z = blockIdx.z;
    const long a_off = (long)z * a_b;
    const long b_off = (long)z * b_b;
    const long c_off = (long)z * c_b;
    const int m0 = blockIdx.y * GBM;
    const int n0 = blockIdx.x * GBN;

    const int tid  = threadIdx.x;
    const int lane = tid & 31;
    const int warp = tid >> 5;
    const int wm = (warp & 3) * 32;
    const int wn = (warp >> 2) * 32;
    const int qr = lane >> 2;
    const int qc = (lane & 3) * 2;
    // ldmatrix lane offsets
    const int a_row = ((lane >> 3) & 1) * 8 + (lane & 7);
    const int a_col = (lane >> 4) * 8;
    const int b_row = ((lane >> 3) & 1) * 8 + (lane & 7);
    const int b_col = ((lane >> 4) & 1) * 8;

    float acc[2][4][4] = {};

    gemm_load_stage(gsm, Ah, Al, a_off, lda, M, m0, Bh, Bl, b_off, ldb, n0, 0, tid);
    CP_COMMIT();

    const int nstage = K / GBK;
    for (int s = 0; s < nstage; s++) {
        CP_WAIT0();
        __syncthreads();
        if (s + 1 < nstage) {
            gemm_load_stage(gsm + ((s + 1) & 1) * STAGE,
                            Ah, Al, a_off, lda, M, m0,
                            Bh, Bl, b_off, ldb, n0, (s + 1) * GBK, tid);
            CP_COMMIT();
        }
        const __nv_bfloat16* As = gsm + (s & 1) * STAGE;
        const __nv_bfloat16* Bs = As + 2 * A_TILE;

        #pragma unroll
        for (int ks = 0; ks < 2; ks++) {
            const int kc = ks * 16;
            uint32_t ah[2][4], al[2][4], bh[2][4], bl[2][4];
            #pragma unroll
            for (int mt = 0; mt < 2; mt++) {
                const __nv_bfloat16* base = As + (wm + mt * 16 + a_row) * ASTR + kc + a_col;
                ldsm4(ah[mt], base);
                ldsm4(al[mt], base + A_TILE);
            }
            #pragma unroll
            for (int ng = 0; ng < 2; ng++) {
                const __nv_bfloat16* base = Bs + (kc + b_row) * BSTR + wn + ng * 16 + b_col;
                ldsm4t(bh[ng], base);
                ldsm4t(bl[ng], base + B_TILE);
            }
            #pragma unroll
            for (int mt = 0; mt < 2; mt++)
                #pragma unroll
                for (int ng = 0; ng < 2; ng++) {
                    mma_bf16(acc[mt][2 * ng    ], ah[mt], bh[ng]);
                    mma_bf16(acc[mt][2 * ng    ], al[mt], bh[ng]);
                    mma_bf16(acc[mt][2 * ng    ], ah[mt], bl[ng]);
                    mma_bf16(acc[mt][2 * ng + 1], ah[mt], bh[ng] + 2);
                    mma_bf16(acc[mt][2 * ng + 1], al[mt], bh[ng] + 2);
                    mma_bf16(acc[mt][2 * ng + 1], ah[mt], bl[ng] + 2);
                }
        }
        __syncthreads();
    }

    // --- epilogue
    #pragma unroll
    for (int mt = 0; mt < 2; mt++) {
        #pragma unroll
        for (int nt = 0; nt < 4; nt++) {
            int r0 = m0 + wm + mt * 16 + qr;
            int r1 = r0 + 8;
            int c  = n0 + wn + nt * 8 + qc;
            float bn0 = 0.f, bn1 = 0.f;
            if (bias_mode == 1) { bn0 = bias[c]; bn1 = bias[c + 1]; }
            float v00 = acc[mt][nt][0] + bn0;
            float v01 = acc[mt][nt][1] + bn1;
            float v10 = acc[mt][nt][2] + bn0;
            float v11 = acc[mt][nt][3] + bn1;
            if (bias_mode == 2) {
                if (r0 < M) { float bm = bias[r0]; v00 += bm; v01 += bm; }
                if (r1 < M) { float bm = bias[r1]; v10 += bm; v11 += bm; }
            }
            if (Ch) {
                __nv_bfloat16 h0, l0, h1, l1;
                if (r0 < M) {
                    split_bf16(v00, h0, l0); split_bf16(v01, h1, l1);
                    *(uint32_t*)(Ch + c_off + (long)r0 * ldc + c) = packb(h0, h1);
                    *(uint32_t*)(Cl + c_off + (long)r0 * ldc + c) = packb(l0, l1);
                }
                if (r1 < M) {
                    split_bf16(v10, h0, l0); split_bf16(v11, h1, l1);
                    *(uint32_t*)(Ch + c_off + (long)r1 * ldc + c) = packb(h0, h1);
                    *(uint32_t*)(Cl + c_off + (long)r1 * ldc + c) = packb(l0, l1);
                }
            } else {
                if (r0 < M) {
                    C[c_off + (long)r0 * ldc + c    ] = v00;
                    C[c_off + (long)r0 * ldc + c + 1] = v01;
                }
                if (r1 < M) {
                    C[c_off + (long)r1 * ldc + c    ] = v10;
                    C[c_off + (long)r1 * ldc + c + 1] = v11;
                }
            }
        }
    }
}

// ---------------- fused flash attention ----------------
#define FSC 0.015625f
#define VKP 72
#define FTILE (64*VKP)
#define FSMEM (2*4*FTILE*2)

__device__ __forceinline__ void flash_load_chunk(
    __nv_bfloat16* buf,
    const __nv_bfloat16* __restrict__ qh_plane,
    const __nv_bfloat16* __restrict__ ql_plane,
    long kbase, long vbase, int c, int tid)
{
    #pragma unroll
    for (int i = 0; i < 16; i++) {
        int e    = tid + i * 128;
        int tile = e >> 9;            // 0=Kh 1=Kl 2=Vh 3=Vl
        int rem  = e & 511;
        int row  = rem >> 3;
        int seg  = rem & 7;
        const __nv_bfloat16* plane = (tile & 1) ? ql_plane : qh_plane;
        long off = ((tile < 2) ? kbase : vbase) + (long)(c * 64 + row) * QKVW + seg * 8;
        cp16(buf + tile * FTILE + row * VKP + seg * 8, plane + off);
    }
}

__global__ __launch_bounds__(128)
void flash_attn(const __nv_bfloat16* __restrict__ qh_plane,
                const __nv_bfloat16* __restrict__ ql_plane,
                __nv_bfloat16* __restrict__ combh,
                __nv_bfloat16* __restrict__ combl)
{
    extern __shared__ __align__(16) __nv_bfloat16 sm[];
    const int z = blockIdx.y;
    const int b = z >> 3, h = z & 7;
    const int m0 = blockIdx.x * 64;
    const int tid  = threadIdx.x;
    const int lane = tid & 31;
    const int warp = tid >> 5;
    const int qr = lane >> 2;
    const int qc = (lane & 3) * 2;

    const long zbase = (long)b * SS * QKVW + h * HD;
    const long kbase = zbase + DD;
    const long vbase = zbase + 2 * DD;

    const int r0 = m0 + warp * 16 + qr;
    uint32_t qh[4][4], ql[4][4];
    #pragma unroll
    for (int ks = 0; ks < 4; ks++) {
        #pragma unroll
        for (int a = 0; a < 4; a++) {
            int row = r0 + (a & 1) * 8;
            int col = ks * 16 + qc + (a >> 1) * 8;
            long off = zbase + (long)row * QKVW + col;
            qh[ks][a] = *(const uint32_t*)(qh_plane + off);
            ql[ks][a] = *(const uint32_t*)(ql_plane + off);
        }
    }

    float o[8][4] = {};
    float m0r = -1e30f, m1r = -1e30f;
    float l0r = 0.f, l1r = 0.f;

    const int skey_off = ((lane >> 4) & 1) * 8 + (lane & 7);
    const int scol_off = ((lane >> 3) & 1) * 8;
    const int vkey_off = ((lane >> 3) & 1) * 8 + (lane & 7);
    const int vcol_off = ((lane >> 4) & 1) * 8;

    flash_load_chunk(sm, qh_plane, ql_plane, kbase, vbase, 0, tid);
    CP_COMMIT();

    for (int c = 0; c < SS / 64; c++) {
        CP_WAIT0();
        __syncthreads();
        if (c + 1 < SS / 64) {
            flash_load_chunk(sm + ((c + 1) & 1) * 4 * FTILE,
                             qh_plane, ql_plane, kbase, vbase, c + 1, tid);
            CP_COMMIT();
        }
        const __nv_bfloat16* Kh_ = sm + (c & 1) * 4 * FTILE;
        const __nv_bfloat16* Vh_ = Kh_ + 2 * FTILE;

        float s[8][4] = {};
        #pragma unroll
        for (int ks = 0; ks < 4; ks++) {
            const int kc = ks * 16;
            #pragma unroll
            for (int ntp = 0; ntp < 4; ntp++) {
                const __nv_bfloat16* base = Kh_ + (ntp * 16 + skey_off) * VKP + kc + scol_off;
                uint32_t bh[4], bl[4];
                ldsm4(bh, base);
                ldsm4(bl, base + FTILE);
                mma_bf16(s[2 * ntp    ], qh[ks], bh);
                mma_bf16(s[2 * ntp    ], ql[ks], bh);
                mma_bf16(s[2 * ntp    ], qh[ks], bl);
                mma_bf16(s[2 * ntp + 1], qh[ks], bh + 2);
                mma_bf16(s[2 * ntp + 1], ql[ks], bh + 2);
                mma_bf16(s[2 * ntp + 1], qh[ks], bl + 2);
            }
        }

        float mx0 = -1e30f, mx1 = -1e30f;
        #pragma unroll
        for (int nt = 0; nt < 8; nt++) {
            mx0 = fmaxf(mx0, fmaxf(s[nt][0], s[nt][1]));
            mx1 = fmaxf(mx1, fmaxf(s[nt][2], s[nt][3]));
        }
        mx0 = fmaxf(mx0, __shfl_xor_sync(0xffffffff, mx0, 1));
        mx0 = fmaxf(mx0, __shfl_xor_sync(0xffffffff, mx0, 2));
        mx1 = fmaxf(mx1, __shfl_xor_sync(0xffffffff, mx1, 1));
        mx1 = fmaxf(mx1, __shfl_xor_sync(0xffffffff, mx1, 2));

        float mn0 = fmaxf(m0r, mx0), mn1 = fmaxf(m1r, mx1);
        float sc0 = __expf((m0r - mn0) * FSC);
        float sc1 = __expf((m1r - mn1) * FSC);
        m0r = mn0; m1r = mn1;

        float sum0 = 0.f, sum1 = 0.f;
        uint32_t ph[4][4], pl[4][4];
        #pragma unroll
        for (int nt = 0; nt < 8; nt++) {
            float p0 = __expf((s[nt][0] - mn0) * FSC);
            float p1 = __expf((s[nt][1] - mn0) * FSC);
            float p2 = __expf((s[nt][2] - mn1) * FSC);
            float p3 = __expf((s[nt][3] - mn1) * FSC);
            sum0 += p0 + p1; sum1 += p2 + p3;
            __nv_bfloat16 h0, lo0, h1, lo1, h2, lo2, h3, lo3;
            split_bf16(p0, h0, lo0); split_bf16(p1, h1, lo1);
            split_bf16(p2, h2, lo2); split_bf16(p3, h3, lo3);
            int ks = nt >> 1, off = (nt & 1) * 2;
            ph[ks][off    ] = packb(h0, h1);
            ph[ks][off + 1] = packb(h2, h3);
            pl[ks][off    ] = packb(lo0, lo1);
            pl[ks][off + 1] = packb(lo2, lo3);
        }
        sum0 += __shfl_xor_sync(0xffffffff, sum0, 1);
        sum0 += __shfl_xor_sync(0xffffffff, sum0, 2);
        sum1 += __shfl_xor_sync(0xffffffff, sum1, 1);
        sum1 += __shfl_xor_sync(0xffffffff, sum1, 2);
        l0r = l0r * sc0 + sum0;
        l1r = l1r * sc1 + sum1;

        #pragma unroll
        for (int nt = 0; nt < 8; nt++) {
            o[nt][0] *= sc0; o[nt][1] *= sc0;
            o[nt][2] *= sc1; o[nt][3] *= sc1;
        }

        #pragma unroll
        for (int ks = 0; ks < 4; ks++) {
            const int kc = ks * 16;
            #pragma unroll
            for (int ntp = 0; ntp < 4; ntp++) {
                const __nv_bfloat16* base = Vh_ + (kc + vkey_off) * VKP + ntp * 16 + vcol_off;
                uint32_t vh4[4], vl4[4];
                ldsm4t(vh4, base);
                ldsm4t(vl4, base + FTILE);
                mma_bf16(o[2 * ntp    ], ph[ks], vh4);
                mma_bf16(o[2 * ntp    ], pl[ks], vh4);
                mma_bf16(o[2 * ntp    ], ph[ks], vl4);
                mma_bf16(o[2 * ntp + 1], ph[ks], vh4 + 2);
                mma_bf16(o[2 * ntp + 1], pl[ks], vh4 + 2);
                mma_bf16(o[2 * ntp + 1], ph[ks], vl4 + 2);
            }
        }
        __syncthreads();
    }

    // --- epilogue: normalize, split to bf16 planes, write concat layout
    float inv0 = 1.f / l0r, inv1 = 1.f / l1r;
    const long cbase = (long)b * SS * DD + h * HD;
    #pragma unroll
    for (int nt = 0; nt < 8; nt++) {
        int col = nt * 8 + qc;
        __nv_bfloat16 h0, l0, h1, l1;
        split_bf16(o[nt][0] * inv0, h0, l0);
        split_bf16(o[nt][1] * inv0, h1, l1);
        *(uint32_t*)(combh + cbase + (long)r0 * DD + col) = packb(h0, h1);
        *(uint32_t*)(combl + cbase + (long)r0 * DD + col) = packb(l0, l1);
        split_bf16(o[nt][2] * inv1, h0, l0);
        split_bf16(o[nt][3] * inv1, h1, l1);
        *(uint32_t*)(combh + cbase + (long)(r0 + 8) * DD + col) = packb(h0, h1);
        *(uint32_t*)(combl + cbase + (long)(r0 + 8) * DD + col) = packb(l0, l1);
    }
}

// ---------------- launch ----------------
extern "C" void kernel_launch(void* const* d_in, const int* in_sizes, int n_in,
                              void* d_out, int out_size)
{
    (void)in_sizes; (void)n_in; (void)out_size;
    const float* x  = (const float*)d_in[0];
    const float* Wq = (const float*)d_in[1];
    const float* bq = (const float*)d_in[2];
    const float* Wk = (const float*)d_in[3];
    const float* bk = (const float*)d_in[4];
    const float* Wv = (const float*)d_in[5];
    const float* bv = (const float*)d_in[6];
    const float* Wt = (const float*)d_in[7];
    const float* bt = (const float*)d_in[8];
    const float* Wo = (const float*)d_in[9];
    const float* bo = (const float*)d_in[10];
    float* out = (float*)d_out;

    __nv_bfloat16 *qkvh, *qkvl, *combh, *combl, *uph, *upl;
    __nv_bfloat16 *xh, *xl, *wph, *wpl, *wth, *wtl, *woh, *wol;
    float *bp;
    cudaGetSymbolAddress((void**)&qkvh,  g_qkvh);
    cudaGetSymbolAddress((void**)&qkvl,  g_qkvl);
    cudaGetSymbolAddress((void**)&combh, g_combh);
    cudaGetSymbolAddress((void**)&combl, g_combl);
    cudaGetSymbolAddress((void**)&uph,   g_uph);
    cudaGetSymbolAddress((void**)&upl,   g_upl);
    cudaGetSymbolAddress((void**)&xh,    g_xh);
    cudaGetSymbolAddress((void**)&xl,    g_xl);
    cudaGetSymbolAddress((void**)&wph,   g_wph);
    cudaGetSymbolAddress((void**)&wpl,   g_wpl);
    cudaGetSymbolAddress((void**)&wth,   g_wth);
    cudaGetSymbolAddress((void**)&wtl,   g_wtl);
    cudaGetSymbolAddress((void**)&woh,   g_woh);
    cudaGetSymbolAddress((void**)&wol,   g_wol);
    cudaGetSymbolAddress((void**)&bp,    g_bp);

    static bool attr_set = false;
    if (!attr_set) {
        cudaFuncSetAttribute(flash_attn,
            cudaFuncAttributeMaxDynamicSharedMemorySize, FSMEM);
        cudaFuncSetAttribute(gemm_planes,
            cudaFuncAttributeMaxDynamicSharedMemorySize, GSMEM);
        attr_set = true;
    }

    // 0) pack everything into bf16 hi/lo planes
    pack_split<<<(NT * II + 255) / 256, 256>>>(x, xh, xl, NT * II);
    pack_qkv_w<<<(3 * II * DD + 255) / 256, 256>>>(Wq, Wk, Wv, wph, wpl);
    pack_split<<<(PP * SS + 255) / 256, 256>>>(Wt, wth, wtl, PP * SS);
    pack_wo_t<<<(II * DD + 255) / 256, 256>>>(Wo, woh, wol);
    pack_qkv_b<<<(QKVW + 255) / 256, 256>>>(bq, bk, bv, bp);

    // 1) fused QKV: [8192,512] @ [512,1536] -> qkv planes
    {
        dim3 grid(QKVW / GBN, NT / GBM, 1);
        gemm_planes<<<grid, 256, GSMEM>>>(NT, QKVW, II,
            xh, xl, 0, II,
            wph, wpl, 0, QKVW,
            nullptr, qkvh, qkvl, 0, QKVW,
            bp, 1);
    }

    // 2) fused attention -> comb planes [B,S,D]
    {
        dim3 grid(SS / 64, BB * HH);
        flash_attn<<<grid, 128, FSMEM>>>(qkvh, qkvl, combh, combl);
    }

    // 3) up[b,p,d] = sum_s Wt[p,s] * comb[b,s,d] + bt[p]  -> up planes
    {
        dim3 grid(DD / GBN, (PP + GBM - 1) / GBM, BB);
        gemm_planes<<<grid, 256, GSMEM>>>(PP, DD, SS,
            wth, wtl, 0, SS,
            combh, combl, (long)SS * DD, DD,
            nullptr, uph, upl, (long)PP * DD, DD,
            bt, 2);
    }

    // 4) out[b,p,o] = sum_d up[b,p,d] * WoT[d,o] + bo[o]  -> fp32 out
    {
        dim3 grid(II / GBN, (PP + GBM - 1) / GBM, BB);
        gemm_planes<<<grid, 256, GSMEM>>>(PP, II, DD,
            uph, upl, (long)PP * DD, DD,
            woh, wol, 0, II,
            out, nullptr, nullptr, (long)PP * II, II,
            bo, 1);
    }
}

// round 6
// speedup vs baseline: 6.1091x; 1.3211x over previous
#include <cuda_runtime.h>
#include <cuda_bf16.h>
#include <math.h>
#include <stdint.h>

// Problem dims
#define BB 4
#define SS 2048
#define II 512
#define DD 512
#define HH 8
#define HD 64
#define PP 720
#define NT (BB*SS)        // 8192 tokens
#define QKVW (3*DD)       // 1536

// ---------------- scratch (__device__ globals, no allocation) ----------------
__device__ __nv_bfloat16 g_qkvh[(size_t)NT * QKVW];
__device__ __nv_bfloat16 g_qkvl[(size_t)NT * QKVW];   // only v-columns used
__device__ __nv_bfloat16 g_combh[(size_t)NT * DD];
__device__ __nv_bfloat16 g_combl[(size_t)NT * DD];
__device__ __nv_bfloat16 g_uph[(size_t)BB * PP * DD];
__device__ __nv_bfloat16 g_upl[(size_t)BB * PP * DD];
__device__ __nv_bfloat16 g_xh[(size_t)NT * II];
__device__ __nv_bfloat16 g_xl[(size_t)NT * II];
__device__ __nv_bfloat16 g_wph[(size_t)II * QKVW];
__device__ __nv_bfloat16 g_wpl[(size_t)II * QKVW];
__device__ __nv_bfloat16 g_wth[(size_t)PP * SS];
__device__ __nv_bfloat16 g_wtl[(size_t)PP * SS];
__device__ __nv_bfloat16 g_woh[(size_t)DD * II];   // transposed: [d][o]
__device__ __nv_bfloat16 g_wol[(size_t)DD * II];
__device__ float g_bp[QKVW];

// ---------------- helpers ----------------
__device__ __forceinline__ void mma_bf16(float* c, const uint32_t* a, const uint32_t* b) {
    asm volatile(
        "mma.sync.aligned.m16n8k16.row.col.f32.bf16.bf16.f32 "
        "{%0,%1,%2,%3}, {%4,%5,%6,%7}, {%8,%9}, {%0,%1,%2,%3};\n"
        : "+f"(c[0]), "+f"(c[1]), "+f"(c[2]), "+f"(c[3])
        : "r"(a[0]), "r"(a[1]), "r"(a[2]), "r"(a[3]), "r"(b[0]), "r"(b[1]));
}
__device__ __forceinline__ void split_bf16(float x, __nv_bfloat16& h, __nv_bfloat16& l) {
    h = __float2bfloat16(x);
    l = __float2bfloat16(x - __bfloat162float(h));
}
__device__ __forceinline__ uint32_t packb(__nv_bfloat16 a, __nv_bfloat16 b) {
    __nv_bfloat162 t; t.x = a; t.y = b;
    return *(uint32_t*)&t;
}
__device__ __forceinline__ void ldsm4(uint32_t* r, const __nv_bfloat16* p) {
    uint32_t a = (uint32_t)__cvta_generic_to_shared(p);
    asm volatile("ldmatrix.sync.aligned.m8n8.x4.shared.b16 {%0,%1,%2,%3}, [%4];\n"
        : "=r"(r[0]), "=r"(r[1]), "=r"(r[2]), "=r"(r[3]) : "r"(a));
}
__device__ __forceinline__ void ldsm4t(uint32_t* r, const __nv_bfloat16* p) {
    uint32_t a = (uint32_t)__cvta_generic_to_shared(p);
    asm volatile("ldmatrix.sync.aligned.m8n8.x4.trans.shared.b16 {%0,%1,%2,%3}, [%4];\n"
        : "=r"(r[0]), "=r"(r[1]), "=r"(r[2]), "=r"(r[3]) : "r"(a));
}
__device__ __forceinline__ void cp16(__nv_bfloat16* dst, const __nv_bfloat16* src) {
    uint32_t d = (uint32_t)__cvta_generic_to_shared(dst);
    asm volatile("cp.async.cg.shared.global [%0], [%1], 16;\n" :: "r"(d), "l"(src));
}
#define CP_COMMIT() asm volatile("cp.async.commit_group;\n")
#define CP_WAIT0()  asm volatile("cp.async.wait_group 0;\n")

// ---------------- pack kernels ----------------
__global__ void pack_split4(const float* __restrict__ src,
                            __nv_bfloat16* __restrict__ dh,
                            __nv_bfloat16* __restrict__ dl, int n4)
{
    int i = blockIdx.x * blockDim.x + threadIdx.x;
    if (i >= n4) return;
    float4 v = ((const float4*)src)[i];
    __nv_bfloat16 h0,l0,h1,l1,h2,l2,h3,l3;
    split_bf16(v.x,h0,l0); split_bf16(v.y,h1,l1);
    split_bf16(v.z,h2,l2); split_bf16(v.w,h3,l3);
    ((uint32_t*)dh)[2*i  ] = packb(h0,h1);
    ((uint32_t*)dh)[2*i+1] = packb(h2,h3);
    ((uint32_t*)dl)[2*i  ] = packb(l0,l1);
    ((uint32_t*)dl)[2*i+1] = packb(l2,l3);
}

__global__ void pack_qkv_w(const float* __restrict__ Wq,
                           const float* __restrict__ Wk,
                           const float* __restrict__ Wv,
                           __nv_bfloat16* __restrict__ dh,
                           __nv_bfloat16* __restrict__ dl)
{
    int idx = blockIdx.x * blockDim.x + threadIdx.x;
    if (idx >= 3 * II * DD) return;
    int m   = idx / (II * DD);
    int rem = idx % (II * DD);          // = h*(512*64) + i*64 + d
    int h   = rem / (II * HD);
    int i   = (rem / HD) % II;
    int d   = rem % HD;
    const float* src = (m == 0) ? Wq : (m == 1) ? Wk : Wv;
    __nv_bfloat16 hi, lo; split_bf16(src[rem], hi, lo);
    long o = (long)i * QKVW + m * DD + h * HD + d;
    dh[o] = hi; dl[o] = lo;
}

__global__ void pack_wo_t(const float* __restrict__ Wo,
                          __nv_bfloat16* __restrict__ dh,
                          __nv_bfloat16* __restrict__ dl)
{
    int idx = blockIdx.x * blockDim.x + threadIdx.x;  // o*DD + d
    if (idx >= II * DD) return;
    int o = idx / DD, d = idx % DD;
    __nv_bfloat16 hi, lo; split_bf16(Wo[idx], hi, lo);
    dh[d * II + o] = hi; dl[d * II + o] = lo;
}

__global__ void pack_qkv_b(const float* __restrict__ bq,
                           const float* __restrict__ bk,
                           const float* __restrict__ bv,
                           float* __restrict__ bp)
{
    int idx = blockIdx.x * blockDim.x + threadIdx.x;
    if (idx >= QKVW) return;
    int m = idx / DD;
    int r = idx % DD;
    const float* src = (m == 0) ? bq : (m == 1) ? bk : bv;
    bp[idx] = src[r];
}

// ---------------- bf16-plane tensor-core GEMM ----------------
// three_term: 1 -> hi/lo 3-mma path; 0 -> hi-only single-mma path.
// Output: fp32 C, or bf16 planes Ch(+Cl); Cl may be null (hi-only store).
#define GBM 128
#define GBN 64
#define GBK 32
#define ASTR 40
#define BSTR 72
#define A_TILE (GBM*ASTR)
#define B_TILE (GBK*BSTR)
#define STAGE (2*A_TILE + 2*B_TILE)
#define GSMEM (2*STAGE*2)

__device__ __forceinline__ void gemm_load_stage(
    __nv_bfloat16* buf,
    const __nv_bfloat16* __restrict__ Ah, const __nv_bfloat16* __restrict__ Al,
    long a_off, int lda, int M, int m0,
    const __nv_bfloat16* __restrict__ Bh, const __nv_bfloat16* __restrict__ Bl,
    long b_off, int ldb, int n0, int k0, int tid, int three_term)
{
    #pragma unroll
    for (int i = 0; i < 4; i++) {
        int e = tid + i * 256;
        int plane = e >> 9;
        if (plane && !three_term) continue;
        int rem = e & 511;
        int m = rem >> 2;
        int seg = rem & 3;
        int mg = m0 + m; if (mg >= M) mg = M - 1;
        const __nv_bfloat16* src = (plane ? Al : Ah) + a_off + (long)mg * lda + k0 + seg * 8;
        cp16(buf + plane * A_TILE + m * ASTR + seg * 8, src);
    }
    #pragma unroll
    for (int i = 0; i < 2; i++) {
        int e = tid + i * 256;
        int plane = e >> 8;
        if (plane && !three_term) continue;
        int rem = e & 255;
        int k = rem >> 3;
        int seg = rem & 7;
        const __nv_bfloat16* src = (plane ? Bl : Bh) + b_off + (long)(k0 + k) * ldb + n0 + seg * 8;
        cp16(buf + 2 * A_TILE + plane * B_TILE + k * BSTR + seg * 8, src);
    }
}

__global__ __launch_bounds__(256)
void gemm_planes(
    int M, int N, int K,
    const __nv_bfloat16* __restrict__ Ah, const __nv_bfloat16* __restrict__ Al,
    long a_b, int lda,
    const __nv_bfloat16* __restrict__ Bh, const __nv_bfloat16* __restrict__ Bl,
    long b_b, int ldb,
    float* __restrict__ C, __nv_bfloat16* __restrict__ Ch, __nv_bfloat16* __restrict__ Cl,
    long c_b, int ldc,
    const float* __restrict__ bias, int bias_mode, int three_term)
{
    extern __shared__ __align__(16) __nv_bfloat16 gsm[];
    const int z = blockIdx.z;
    const long a_off = (long)z * a_b;
    const long b_off = (long)z * b_b;
    const long c_off = (long)z * c_b;
    const int m0 = blockIdx.y * GBM;
    const int n0 = blockIdx.x * GBN;

    const int tid  = threadIdx.x;
    const int lane = tid & 31;
    const int warp = tid >> 5;
    const int wm = (warp & 3) * 32;
    const int wn = (warp >> 2) * 32;
    const int qr = lane >> 2;
    const int qc = (lane & 3) * 2;
    const int a_row = ((lane >> 3) & 1) * 8 + (lane & 7);
    const int a_col = (lane >> 4) * 8;
    const int b_row = ((lane >> 3) & 1) * 8 + (lane & 7);
    const int b_col = ((lane >> 4) & 1) * 8;

    float acc[2][4][4] = {};

    gemm_load_stage(gsm, Ah, Al, a_off, lda, M, m0, Bh, Bl, b_off, ldb, n0, 0, tid, three_term);
    CP_COMMIT();

    const int nstage = K / GBK;
    for (int s = 0; s < nstage; s++) {
        CP_WAIT0();
        __syncthreads();
        if (s + 1 < nstage) {
            gemm_load_stage(gsm + ((s + 1) & 1) * STAGE,
                            Ah, Al, a_off, lda, M, m0,
                            Bh, Bl, b_off, ldb, n0, (s + 1) * GBK, tid, three_term);
            CP_COMMIT();
        }
        const __nv_bfloat16* As = gsm + (s & 1) * STAGE;
        const __nv_bfloat16* Bs = As + 2 * A_TILE;

        #pragma unroll
        for (int ks = 0; ks < 2; ks++) {
            const int kc = ks * 16;
            uint32_t ah[2][4], al[2][4], bh[2][4], bl[2][4];
            #pragma unroll
            for (int mt = 0; mt < 2; mt++) {
                const __nv_bfloat16* base = As + (wm + mt * 16 + a_row) * ASTR + kc + a_col;
                ldsm4(ah[mt], base);
                if (three_term) ldsm4(al[mt], base + A_TILE);
            }
            #pragma unroll
            for (int ng = 0; ng < 2; ng++) {
                const __nv_bfloat16* base = Bs + (kc + b_row) * BSTR + wn + ng * 16 + b_col;
                ldsm4t(bh[ng], base);
                if (three_term) ldsm4t(bl[ng], base + B_TILE);
            }
            #pragma unroll
            for (int mt = 0; mt < 2; mt++)
                #pragma unroll
                for (int ng = 0; ng < 2; ng++) {
                    mma_bf16(acc[mt][2 * ng    ], ah[mt], bh[ng]);
                    mma_bf16(acc[mt][2 * ng + 1], ah[mt], bh[ng] + 2);
                    if (three_term) {
                        mma_bf16(acc[mt][2 * ng    ], al[mt], bh[ng]);
                        mma_bf16(acc[mt][2 * ng    ], ah[mt], bl[ng]);
                        mma_bf16(acc[mt][2 * ng + 1], al[mt], bh[ng] + 2);
                        mma_bf16(acc[mt][2 * ng + 1], ah[mt], bl[ng] + 2);
                    }
                }
        }
        __syncthreads();
    }

    // --- epilogue
    #pragma unroll
    for (int mt = 0; mt < 2; mt++) {
        #pragma unroll
        for (int nt = 0; nt < 4; nt++) {
            int r0 = m0 + wm + mt * 16 + qr;
            int r1 = r0 + 8;
            int c  = n0 + wn + nt * 8 + qc;
            float bn0 = 0.f, bn1 = 0.f;
            if (bias_mode == 1) { bn0 = bias[c]; bn1 = bias[c + 1]; }
            float v00 = acc[mt][nt][0] + bn0;
            float v01 = acc[mt][nt][1] + bn1;
            float v10 = acc[mt][nt][2] + bn0;
            float v11 = acc[mt][nt][3] + bn1;
            if (bias_mode == 2) {
                if (r0 < M) { float bm = bias[r0]; v00 += bm; v01 += bm; }
                if (r1 < M) { float bm = bias[r1]; v10 += bm; v11 += bm; }
            }
            if (Ch && Cl) {
                __nv_bfloat16 h0, l0, h1, l1;
                if (r0 < M) {
                    split_bf16(v00, h0, l0); split_bf16(v01, h1, l1);
                    *(uint32_t*)(Ch + c_off + (long)r0 * ldc + c) = packb(h0, h1);
                    *(uint32_t*)(Cl + c_off + (long)r0 * ldc + c) = packb(l0, l1);
                }
                if (r1 < M) {
                    split_bf16(v10, h0, l0); split_bf16(v11, h1, l1);
                    *(uint32_t*)(Ch + c_off + (long)r1 * ldc + c) = packb(h0, h1);
                    *(uint32_t*)(Cl + c_off + (long)r1 * ldc + c) = packb(l0, l1);
                }
            } else if (Ch) {
                if (r0 < M)
                    *(uint32_t*)(Ch + c_off + (long)r0 * ldc + c) =
                        packb(__float2bfloat16(v00), __float2bfloat16(v01));
                if (r1 < M)
                    *(uint32_t*)(Ch + c_off + (long)r1 * ldc + c) =
                        packb(__float2bfloat16(v10), __float2bfloat16(v11));
            } else {
                if (r0 < M) {
                    C[c_off + (long)r0 * ldc + c    ] = v00;
                    C[c_off + (long)r0 * ldc + c + 1] = v01;
                }
                if (r1 < M) {
                    C[c_off + (long)r1 * ldc + c    ] = v10;
                    C[c_off + (long)r1 * ldc + c + 1] = v11;
                }
            }
        }
    }
}

// ---------------- fused flash attention ----------------
// S = Q K^T in 1-term bf16 (exponent abs-accuracy argument); P V in 3-term.
#define FSC 0.015625f
#define VKP 72
#define FTILE (64*VKP)
#define NTILES 3          // Kh, Vh, Vl
#define FSMEM (2*NTILES*FTILE*2)

__device__ __forceinline__ void flash_load_chunk(
    __nv_bfloat16* buf,
    const __nv_bfloat16* __restrict__ qh_plane,
    const __nv_bfloat16* __restrict__ ql_plane,
    long kbase, long vbase, int c, int tid)
{
    #pragma unroll
    for (int i = 0; i < 12; i++) {
        int e    = tid + i * 128;
        int tile = e >> 9;            // 0=Kh 1=Vh 2=Vl
        int rem  = e & 511;
        int row  = rem >> 3;
        int seg  = rem & 7;
        const __nv_bfloat16* plane = (tile == 2) ? ql_plane : qh_plane;
        long off = ((tile == 0) ? kbase : vbase) + (long)(c * 64 + row) * QKVW + seg * 8;
        cp16(buf + tile * FTILE + row * VKP + seg * 8, plane + off);
    }
}

__global__ __launch_bounds__(128)
void flash_attn(const __nv_bfloat16* __restrict__ qh_plane,
                const __nv_bfloat16* __restrict__ ql_plane,
                __nv_bfloat16* __restrict__ combh,
                __nv_bfloat16* __restrict__ combl)
{
    extern __shared__ __align__(16) __nv_bfloat16 sm[];
    const int z = blockIdx.y;
    const int b = z >> 3, h = z & 7;
    const int m0 = blockIdx.x * 64;
    const int tid  = threadIdx.x;
    const int lane = tid & 31;
    const int warp = tid >> 5;
    const int qr = lane >> 2;
    const int qc = (lane & 3) * 2;

    const long zbase = (long)b * SS * QKVW + h * HD;
    const long kbase = zbase + DD;
    const long vbase = zbase + 2 * DD;

    const int r0 = m0 + warp * 16 + qr;
    uint32_t qh[4][4];
    #pragma unroll
    for (int ks = 0; ks < 4; ks++) {
        #pragma unroll
        for (int a = 0; a < 4; a++) {
            int row = r0 + (a & 1) * 8;
            int col = ks * 16 + qc + (a >> 1) * 8;
            qh[ks][a] = *(const uint32_t*)(qh_plane + zbase + (long)row * QKVW + col);
        }
    }

    float o[8][4] = {};
    float m0r = -1e30f, m1r = -1e30f;
    float l0r = 0.f, l1r = 0.f;

    const int skey_off = ((lane >> 4) & 1) * 8 + (lane & 7);
    const int scol_off = ((lane >> 3) & 1) * 8;
    const int vkey_off = ((lane >> 3) & 1) * 8 + (lane & 7);
    const int vcol_off = ((lane >> 4) & 1) * 8;

    flash_load_chunk(sm, qh_plane, ql_plane, kbase, vbase, 0, tid);
    CP_COMMIT();

    for (int c = 0; c < SS / 64; c++) {
        CP_WAIT0();
        __syncthreads();
        if (c + 1 < SS / 64) {
            flash_load_chunk(sm + ((c + 1) & 1) * NTILES * FTILE,
                             qh_plane, ql_plane, kbase, vbase, c + 1, tid);
            CP_COMMIT();
        }
        const __nv_bfloat16* Kh_ = sm + (c & 1) * NTILES * FTILE;
        const __nv_bfloat16* Vh_ = Kh_ + FTILE;

        // --- S = Q K^T (1-term)
        float s[8][4] = {};
        #pragma unroll
        for (int ks = 0; ks < 4; ks++) {
            const int kc = ks * 16;
            #pragma unroll
            for (int ntp = 0; ntp < 4; ntp++) {
                const __nv_bfloat16* base = Kh_ + (ntp * 16 + skey_off) * VKP + kc + scol_off;
                uint32_t bh[4];
                ldsm4(bh, base);
                mma_bf16(s[2 * ntp    ], qh[ks], bh);
                mma_bf16(s[2 * ntp + 1], qh[ks], bh + 2);
            }
        }

        // --- online softmax
        float mx0 = -1e30f, mx1 = -1e30f;
        #pragma unroll
        for (int nt = 0; nt < 8; nt++) {
            mx0 = fmaxf(mx0, fmaxf(s[nt][0], s[nt][1]));
            mx1 = fmaxf(mx1, fmaxf(s[nt][2], s[nt][3]));
        }
        mx0 = fmaxf(mx0, __shfl_xor_sync(0xffffffff, mx0, 1));
        mx0 = fmaxf(mx0, __shfl_xor_sync(0xffffffff, mx0, 2));
        mx1 = fmaxf(mx1, __shfl_xor_sync(0xffffffff, mx1, 1));
        mx1 = fmaxf(mx1, __shfl_xor_sync(0xffffffff, mx1, 2));

        float mn0 = fmaxf(m0r, mx0), mn1 = fmaxf(m1r, mx1);
        float sc0 = __expf((m0r - mn0) * FSC);
        float sc1 = __expf((m1r - mn1) * FSC);
        m0r = mn0; m1r = mn1;

        float sum0 = 0.f, sum1 = 0.f;
        uint32_t ph[4][4], pl[4][4];
        #pragma unroll
        for (int nt = 0; nt < 8; nt++) {
            float p0 = __expf((s[nt][0] - mn0) * FSC);
            float p1 = __expf((s[nt][1] - mn0) * FSC);
            float p2 = __expf((s[nt][2] - mn1) * FSC);
            float p3 = __expf((s[nt][3] - mn1) * FSC);
            sum0 += p0 + p1; sum1 += p2 + p3;
            __nv_bfloat16 h0, lo0, h1, lo1, h2, lo2, h3, lo3;
            split_bf16(p0, h0, lo0); split_bf16(p1, h1, lo1);
            split_bf16(p2, h2, lo2); split_bf16(p3, h3, lo3);
            int ks = nt >> 1, off = (nt & 1) * 2;
            ph[ks][off    ] = packb(h0, h1);
            ph[ks][off + 1] = packb(h2, h3);
            pl[ks][off    ] = packb(lo0, lo1);
            pl[ks][off + 1] = packb(lo2, lo3);
        }
        sum0 += __shfl_xor_sync(0xffffffff, sum0, 1);
        sum0 += __shfl_xor_sync(0xffffffff, sum0, 2);
        sum1 += __shfl_xor_sync(0xffffffff, sum1, 1);
        sum1 += __shfl_xor_sync(0xffffffff, sum1, 2);
        l0r = l0r * sc0 + sum0;
        l1r = l1r * sc1 + sum1;

        #pragma unroll
        for (int nt = 0; nt < 8; nt++) {
            o[nt][0] *= sc0; o[nt][1] *= sc0;
            o[nt][2] *= sc1; o[nt][3] *= sc1;
        }

        // --- O += P V (3-term)
        #pragma unroll
        for (int ks = 0; ks < 4; ks++) {
            const int kc = ks * 16;
            #pragma unroll
            for (int ntp = 0; ntp < 4; ntp++) {
                const __nv_bfloat16* base = Vh_ + (kc + vkey_off) * VKP + ntp * 16 + vcol_off;
                uint32_t vh4[4], vl4[4];
                ldsm4t(vh4, base);
                ldsm4t(vl4, base + FTILE);
                mma_bf16(o[2 * ntp    ], ph[ks], vh4);
                mma_bf16(o[2 * ntp    ], pl[ks], vh4);
                mma_bf16(o[2 * ntp    ], ph[ks], vl4);
                mma_bf16(o[2 * ntp + 1], ph[ks], vh4 + 2);
                mma_bf16(o[2 * ntp + 1], pl[ks], vh4 + 2);
                mma_bf16(o[2 * ntp + 1], ph[ks], vl4 + 2);
            }
        }
        __syncthreads();
    }

    // --- epilogue
    float inv0 = 1.f / l0r, inv1 = 1.f / l1r;
    const long cbase = (long)b * SS * DD + h * HD;
    #pragma unroll
    for (int nt = 0; nt < 8; nt++) {
        int col = nt * 8 + qc;
        __nv_bfloat16 h0, l0, h1, l1;
        split_bf16(o[nt][0] * inv0, h0, l0);
        split_bf16(o[nt][1] * inv0, h1, l1);
        *(uint32_t*)(combh + cbase + (long)r0 * DD + col) = packb(h0, h1);
        *(uint32_t*)(combl + cbase + (long)r0 * DD + col) = packb(l0, l1);
        split_bf16(o[nt][2] * inv1, h0, l0);
        split_bf16(o[nt][3] * inv1, h1, l1);
        *(uint32_t*)(combh + cbase + (long)(r0 + 8) * DD + col) = packb(h0, h1);
        *(uint32_t*)(combl + cbase + (long)(r0 + 8) * DD + col) = packb(l0, l1);
    }
}

// ---------------- launch ----------------
extern "C" void kernel_launch(void* const* d_in, const int* in_sizes, int n_in,
                              void* d_out, int out_size)
{
    (void)in_sizes; (void)n_in; (void)out_size;
    const float* x  = (const float*)d_in[0];
    const float* Wq = (const float*)d_in[1];
    const float* bq = (const float*)d_in[2];
    const float* Wk = (const float*)d_in[3];
    const float* bk = (const float*)d_in[4];
    const float* Wv = (const float*)d_in[5];
    const float* bv = (const float*)d_in[6];
    const float* Wt = (const float*)d_in[7];
    const float* bt = (const float*)d_in[8];
    const float* Wo = (const float*)d_in[9];
    const float* bo = (const float*)d_in[10];
    float* out = (float*)d_out;

    __nv_bfloat16 *qkvh, *qkvl, *combh, *combl, *uph, *upl;
    __nv_bfloat16 *xh, *xl, *wph, *wpl, *wth, *wtl, *woh, *wol;
    float *bp;
    cudaGetSymbolAddress((void**)&qkvh,  g_qkvh);
    cudaGetSymbolAddress((void**)&qkvl,  g_qkvl);
    cudaGetSymbolAddress((void**)&combh, g_combh);
    cudaGetSymbolAddress((void**)&combl, g_combl);
    cudaGetSymbolAddress((void**)&uph,   g_uph);
    cudaGetSymbolAddress((void**)&upl,   g_upl);
    cudaGetSymbolAddress((void**)&xh,    g_xh);
    cudaGetSymbolAddress((void**)&xl,    g_xl);
    cudaGetSymbolAddress((void**)&wph,   g_wph);
    cudaGetSymbolAddress((void**)&wpl,   g_wpl);
    cudaGetSymbolAddress((void**)&wth,   g_wth);
    cudaGetSymbolAddress((void**)&wtl,   g_wtl);
    cudaGetSymbolAddress((void**)&woh,   g_woh);
    cudaGetSymbolAddress((void**)&wol,   g_wol);
    cudaGetSymbolAddress((void**)&bp,    g_bp);

    static bool attr_set = false;
    if (!attr_set) {
        cudaFuncSetAttribute(flash_attn,
            cudaFuncAttributeMaxDynamicSharedMemorySize, FSMEM);
        cudaFuncSetAttribute(gemm_planes,
            cudaFuncAttributeMaxDynamicSharedMemorySize, GSMEM);
        attr_set = true;
    }

    // 0) packs
    pack_split4<<<(NT * II / 4 + 255) / 256, 256>>>(x, xh, xl, NT * II / 4);
    pack_qkv_w<<<(3 * II * DD + 255) / 256, 256>>>(Wq, Wk, Wv, wph, wpl);
    pack_split4<<<(PP * SS / 4 + 255) / 256, 256>>>(Wt, wth, wtl, PP * SS / 4);
    pack_wo_t<<<(II * DD + 255) / 256, 256>>>(Wo, woh, wol);
    pack_qkv_b<<<(QKVW + 255) / 256, 256>>>(bq, bk, bv, bp);

    // 1a) QK projection: [8192,512] @ [512,1024], 1-term, hi-only output
    {
        dim3 grid(2 * DD / GBN, NT / GBM, 1);
        gemm_planes<<<grid, 256, GSMEM>>>(NT, 2 * DD, II,
            xh, xl, 0, II,
            wph, wpl, 0, QKVW,
            nullptr, qkvh, nullptr, 0, QKVW,
            bp, 1, 0);
    }
    // 1b) V projection: [8192,512] @ [512,512], 3-term, hi/lo output
    {
        dim3 grid(DD / GBN, NT / GBM, 1);
        gemm_planes<<<grid, 256, GSMEM>>>(NT, DD, II,
            xh, xl, 0, II,
            wph + 2 * DD, wpl + 2 * DD, 0, QKVW,
            nullptr, qkvh + 2 * DD, qkvl + 2 * DD, 0, QKVW,
            bp + 2 * DD, 1, 1);
    }

    // 2) fused attention -> comb planes [B,S,D]
    {
        dim3 grid(SS / 64, BB * HH);
        flash_attn<<<grid, 128, FSMEM>>>(qkvh, qkvl, combh, combl);
    }

    // 3) temporal: up[b,p,d] = sum_s Wt[p,s] * comb[b,s,d] + bt[p]
    {
        dim3 grid(DD / GBN, (PP + GBM - 1) / GBM, BB);
        gemm_planes<<<grid, 256, GSMEM>>>(PP, DD, SS,
            wth, wtl, 0, SS,
            combh, combl, (long)SS * DD, DD,
            nullptr, uph, upl, (long)PP * DD, DD,
            bt, 2, 1);
    }

    // 4) out[b,p,o] = sum_d up[b,p,d] * WoT[d,o] + bo[o]
    {
        dim3 grid(II / GBN, (PP + GBM - 1) / GBM, BB);
        gemm_planes<<<grid, 256, GSMEM>>>(PP, II, DD,
            uph, upl, (long)PP * DD, DD,
            woh, wol, 0, II,
            out, nullptr, nullptr, (long)PP * II, II,
            bo, 1, 1);
    }
}